// round 11
// baseline (speedup 1.0000x reference)
#include <cuda_runtime.h>
#include <cuda_fp16.h>
#include <math.h>
#include <stdint.h>

#define NSRC 4096
#define NTGT 4096
#define DIM  512
#define KSPL 1536          // 3-product fp16 split-K (err ~1e-8, = fp32 baseline)
#define NCLS 64
#define KNN  10
#define RK   20
#define TOPN 2048
#define TAU  0.05f
#define EPSL 1e-6f

#define FORD_NEGINF 0x007FFFFFu

// ---------------- scratch (device globals; allocation-free) ----------------
__device__ __half g_T16 [(size_t)NTGT * KSPL];  // T  split [a0|a0|a1]
__device__ __half g_T016[(size_t)NTGT * KSPL];  // T0 split [a0|a0|a1]
__device__ __half g_S16 [(size_t)NSRC * KSPL];  // S  split [b0|b1|b0] (shared B)
__device__ float g_simT [ (size_t)NTGT * NSRC ];
__device__ float g_sim0T[ (size_t)NTGT * NSRC ];
__device__ int   g_assigned[NTGT];
__device__ float g_scores[NTGT];
__device__ int   g_sel[NTGT];
__device__ float g_logt[NTGT];
__device__ int   g_nc;

// ---------------- helpers ---------------------------------------------------
__device__ __forceinline__ unsigned int ford(float f) {
    unsigned int u = __float_as_uint(f);
    return (u & 0x80000000u) ? ~u : (u | 0x80000000u);
}
__device__ __forceinline__ unsigned long long wmax(unsigned long long k) {
    #pragma unroll
    for (int o = 16; o; o >>= 1) {
        unsigned long long t = __shfl_xor_sync(0xffffffffu, k, o);
        if (t > k) k = t;
    }
    return k;
}
__device__ __forceinline__ uint32_t smem_u32(const void* p) {
    uint32_t a;
    asm("{ .reg .u64 t; cvta.to.shared.u64 t, %1; cvt.u32.u64 %0, t; }" : "=r"(a) : "l"(p));
    return a;
}
__device__ __forceinline__ void ldsm4(uint32_t* r, uint32_t addr) {
    asm volatile("ldmatrix.sync.aligned.m8n8.x4.shared.b16 {%0,%1,%2,%3}, [%4];"
        : "=r"(r[0]), "=r"(r[1]), "=r"(r[2]), "=r"(r[3]) : "r"(addr));
}
__device__ __forceinline__ void mma16816(float* c, const uint32_t* a, const uint32_t* b) {
    asm volatile("mma.sync.aligned.m16n8k16.row.col.f32.f16.f16.f32 "
        "{%0,%1,%2,%3}, {%4,%5,%6,%7}, {%8,%9}, {%0,%1,%2,%3};"
        : "+f"(c[0]), "+f"(c[1]), "+f"(c[2]), "+f"(c[3])
        : "r"(a[0]), "r"(a[1]), "r"(a[2]), "r"(a[3]), "r"(b[0]), "r"(b[1]));
}
#define CP_A16(dst, src) \
    asm volatile("cp.async.cg.shared.global [%0], [%1], 16;" :: "r"(dst), "l"(src) : "memory")
#define CP_COMMIT() asm volatile("cp.async.commit_group;" ::: "memory")
#define CP_WAIT1()  asm volatile("cp.async.wait_group 1;" ::: "memory")

// 32-element masked argmax over ordered-uint keys (lowest index wins ties)
__device__ __forceinline__ void scan32(const uint32_t* u, unsigned alive,
                                       uint32_t& best, int& bi) {
    best = 0u; bi = 0;
    #pragma unroll
    for (int i = 0; i < 32; ++i) {
        const uint32_t x = ((alive >> i) & 1u) ? u[i] : 0u;
        if (x > best) { best = x; bi = i; }
    }
}

// ---------------- 1. normalize rows + fp16 2-component split emission ------
__global__ void __launch_bounds__(128) normalize_k(
    const float* __restrict__ src, const float* __restrict__ tgt,
    const float* __restrict__ tgt0)
{
    const int r = blockIdx.x;
    const int m = blockIdx.y;
    if (r == 0 && m == 0 && threadIdx.x == 0) g_nc = 0;

    const float* in = (m == 0) ? src : (m == 1) ? tgt : tgt0;

    const float4 v = ((const float4*)(in + (size_t)r * DIM))[threadIdx.x];
    float s = v.x*v.x + v.y*v.y + v.z*v.z + v.w*v.w;
    #pragma unroll
    for (int o = 16; o; o >>= 1) s += __shfl_down_sync(0xffffffffu, s, o);
    __shared__ float ws[4];
    if ((threadIdx.x & 31) == 0) ws[threadIdx.x >> 5] = s;
    __syncthreads();
    const float inv = 1.0f / sqrtf(ws[0] + ws[1] + ws[2] + ws[3]);
    float o4[4] = { v.x * inv, v.y * inv, v.z * inv, v.w * inv };

    __half c0[4], c1[4];
    #pragma unroll
    for (int t = 0; t < 4; ++t) {
        c0[t] = __float2half_rn(o4[t]);
        c1[t] = __float2half_rn(o4[t] - __half2float(c0[t]));
    }
    const int c = threadIdx.x * 4;
    if (m == 0) {            // source S (shared B): [b0 | b1 | b0]
        __half* p = g_S16 + (size_t)r * KSPL;
        #pragma unroll
        for (int t = 0; t < 4; ++t) {
            p[c+t] = c0[t]; p[c+t+512] = c1[t]; p[c+t+1024] = c0[t];
        }
    } else {                 // T / T0: [a0 | a0 | a1]
        __half* p = ((m == 1) ? g_T16 : g_T016) + (size_t)r * KSPL;
        #pragma unroll
        for (int t = 0; t < 4; ++t) {
            p[c+t] = c0[t]; p[c+t+512] = c0[t]; p[c+t+1024] = c1[t];
        }
    }
}

// ---------------- 2. fp16 mma.sync GEMM, warp-tile 64x64 -------------------
// 128x128 CTA tile, 4 warps (2x2), K step 32, 3-stage cp.async pipeline.
// B fragments via ldsm4 (n16 x k16 per op) -> LDSM:MMA ratio 1:4.
#define ST_BYTES 20480
#define GEMM_SMEM (3 * ST_BYTES)   // 61440
__global__ void __launch_bounds__(128) gemm_f16(int which, int K)
{
    extern __shared__ char sm[];
    const __half* __restrict__ A = which ? g_T016 : g_T16;
    const __half* __restrict__ B = g_S16;
    float* __restrict__ C = which ? g_sim0T : g_simT;

    const int tid = threadIdx.x;
    const int bm = blockIdx.y * 128;
    const int bn = blockIdx.x * 128;

    // loader: thread t owns A row t and B row t (64B each = 4 cp16)
    const __half* Ag = A + (size_t)(bm + tid) * K;
    const __half* Bg = B + (size_t)(bn + tid) * K;

    const uint32_t sbase = smem_u32(sm);
    const uint32_t awr = sbase + (uint32_t)tid * 80u;
    const uint32_t bwr = awr + 10240u;

    const int w = tid >> 5, lane = tid & 31;
    const int wm = (w >> 1) * 64;
    const int wn = (w & 1) * 64;
    // A frag addr (validated map): lanes 0-15 rows +0B, 16-31 rows +16B
    const uint32_t aoff = (uint32_t)(wm + (lane & 15)) * 80u + (uint32_t)(lane >> 4) * 16u;
    // B frag addr for ldsm4 n16k16: lanes 0-7 n(0..8)+0B, 8-15 n(0..8)+16B,
    //                                16-23 n(8..16)+0B, 24-31 n(8..16)+16B
    const uint32_t boff = 10240u + (uint32_t)(wn + ((lane >> 4) << 3) + (lane & 7)) * 80u
                        + (uint32_t)((lane >> 3) & 1) * 16u;

    const int NKT = K >> 5;

    #pragma unroll
    for (int t = 0; t < 2; ++t) {
        const uint32_t st = (uint32_t)t * ST_BYTES;
        const __half* as = Ag + t * 32;
        const __half* bs = Bg + t * 32;
        #pragma unroll
        for (int q = 0; q < 4; ++q) {
            CP_A16(awr + st + (uint32_t)q * 16u, as + q * 8);
            CP_A16(bwr + st + (uint32_t)q * 16u, bs + q * 8);
        }
        CP_COMMIT();
    }

    float acc[4][8][4];
    #pragma unroll
    for (int mi = 0; mi < 4; ++mi)
        #pragma unroll
        for (int ni = 0; ni < 8; ++ni)
            #pragma unroll
            for (int t = 0; t < 4; ++t) acc[mi][ni][t] = 0.0f;

    #pragma unroll 1
    for (int kt = 0; kt < NKT; ++kt) {
        CP_WAIT1();
        __syncthreads();
        if (kt + 2 < NKT) {
            const uint32_t st = (uint32_t)((kt + 2) % 3) * ST_BYTES;
            const __half* as = Ag + (kt + 2) * 32;
            const __half* bs = Bg + (kt + 2) * 32;
            #pragma unroll
            for (int q = 0; q < 4; ++q) {
                CP_A16(awr + st + (uint32_t)q * 16u, as + q * 8);
                CP_A16(bwr + st + (uint32_t)q * 16u, bs + q * 8);
            }
        }
        CP_COMMIT();

        const uint32_t st = (uint32_t)(kt % 3) * ST_BYTES;
        const uint32_t abase = sbase + st + aoff;
        const uint32_t bbase = sbase + st + boff;
        #pragma unroll
        for (int kc = 0; kc < 2; ++kc) {
            uint32_t afr[4][4], bq[4][4];
            #pragma unroll
            for (int mi = 0; mi < 4; ++mi)
                ldsm4(afr[mi], abase + (uint32_t)mi * (16u * 80u) + (uint32_t)kc * 32u);
            #pragma unroll
            for (int q = 0; q < 4; ++q)
                ldsm4(bq[q], bbase + (uint32_t)q * (16u * 80u) + (uint32_t)kc * 32u);
            #pragma unroll
            for (int mi = 0; mi < 4; ++mi)
                #pragma unroll
                for (int ni = 0; ni < 8; ++ni)
                    mma16816(acc[mi][ni], afr[mi], &bq[ni >> 1][(ni & 1) * 2]);
        }
    }

    // epilogue: c0,c1 -> (row, col..col+1); c2,c3 -> (row+8, ...)
    const int rbase = bm + wm + (lane >> 2);
    const int cbase = bn + wn + (lane & 3) * 2;
    #pragma unroll
    for (int mi = 0; mi < 4; ++mi) {
        #pragma unroll
        for (int ni = 0; ni < 8; ++ni) {
            const int rr = rbase + mi * 16;
            const int cc = cbase + ni * 8;
            *(float2*)(C + (size_t)rr * NSRC + cc)       = make_float2(acc[mi][ni][0], acc[mi][ni][1]);
            *(float2*)(C + (size_t)(rr + 8) * NSRC + cc) = make_float2(acc[mi][ni][2], acc[mi][ni][3]);
        }
    }
}

// ---------------- 3. selection: 2 targets/block, 4 warps each --------------
// Same redux/ballot/cached-argmax structure as R9 (validated), generalized to
// 32 items/thread and two independent targets sharing one block's smem.
__global__ void __launch_bounds__(256) rank_kernel(
    const int* __restrict__ slab, const int* __restrict__ tlab)
{
    const int tid  = threadIdx.x;
    const int lane = tid & 31;
    const int w    = tid >> 5;
    const int tgt  = w >> 2;      // 0 or 1
    const int wt   = w & 3;       // warp within target
    const int j    = blockIdx.x * 2 + tgt;

    __shared__ float s_sim0[2][NSRC];
    __shared__ unsigned char s_lab[NSRC];
    __shared__ unsigned long long s_k10[2][40];
    __shared__ unsigned long long s_k20[2][2][80];
    __shared__ int   s_t10[2][KNN];
    __shared__ int   s_a[2];
    __shared__ float s_sum[2][2];

    const float* s0a = g_sim0T + (size_t)(blockIdx.x * 2) * NSRC;

    #pragma unroll
    for (int t = 0; t < 4; ++t) {
        const int i = tid + t * 256;
        ((float4*)s_sim0[0])[i] = ((const float4*)s0a)[i];
        ((float4*)s_sim0[1])[i] = ((const float4*)(s0a + NSRC))[i];
        int4 lb = ((const int4*)slab)[i];
        uchar4 uu;
        uu.x = (unsigned char)lb.x; uu.y = (unsigned char)lb.y;
        uu.z = (unsigned char)lb.z; uu.w = (unsigned char)lb.w;
        ((uchar4*)s_lab)[i] = uu;
    }

    const int base = wt * 1024 + lane * 32;
    uint32_t u[32];
    {
        const float4* rp = (const float4*)(g_simT + (size_t)j * NSRC + base);
        #pragma unroll
        for (int q = 0; q < 8; ++q) {
            float4 vv = rp[q];
            u[q*4+0] = ford(vv.x); u[q*4+1] = ford(vv.y);
            u[q*4+2] = ford(vv.z); u[q*4+3] = ford(vv.w);
        }
    }

    // ---- per-warp top-10 over 1024 items ----
    {
        unsigned alive = 0xFFFFFFFFu;
        uint32_t best; int bi;
        scan32(u, alive, best, bi);
        #pragma unroll 1
        for (int it = 0; it < KNN; ++it) {
            const uint32_t m = __reduce_max_sync(0xffffffffu, best);
            const unsigned msk = __ballot_sync(0xffffffffu, best == m);
            const int src = __ffs(msk) - 1;
            const int widx = __shfl_sync(0xffffffffu, base + bi, src);
            if (lane == 0)
                s_k10[tgt][wt * KNN + it] =
                    ((unsigned long long)m << 12) | (unsigned)(4095 - widx);
            if (lane == src) {
                alive &= ~(1u << bi);
                scan32(u, alive, best, bi);
            }
        }
    }
    __syncthreads();

    // ---- warps 0 / 4: merge 40 candidates -> global top-10, assign --------
    if (wt == 0) {
        const unsigned long long* keys = s_k10[tgt];
        unsigned long long mk[2];
        mk[0] = keys[lane];
        mk[1] = (lane < 8) ? keys[lane + 32] : 0ull;
        unsigned int al = 3u;
        #pragma unroll 1
        for (int it = 0; it < KNN; ++it) {
            unsigned long long b = 0ull;
            #pragma unroll
            for (int t = 0; t < 2; ++t)
                if ((al >> t) & 1u) b = (mk[t] > b) ? mk[t] : b;
            unsigned long long key = wmax(b);
            if (lane == 0) s_t10[tgt][it] = 4095 - (int)(key & 0xFFFu);
            #pragma unroll
            for (int t = 0; t < 2; ++t)
                if (mk[t] == key) al &= ~(1u << t);
        }
        if (lane == 0) {
            int cls[KNN];
            #pragma unroll
            for (int k = 0; k < KNN; ++k) cls[k] = s_lab[s_t10[tgt][k]];
            int bestc = 1000, bestn = 0;
            #pragma unroll 1
            for (int k = 0; k < KNN; ++k) {
                int n = 0;
                #pragma unroll
                for (int l = 0; l < KNN; ++l) n += (cls[l] == cls[k]);
                if (n > bestn || (n == bestn && cls[k] < bestc)) { bestn = n; bestc = cls[k]; }
            }
            s_a[tgt] = bestc;
            g_assigned[j] = bestc;
            if (bestc == tlab[j]) atomicAdd(&g_nc, 1);
        }
    }
    __syncthreads();
    const int a = s_a[tgt];

    // ---- per-warp masked top-20 (in-class / out-of-class) -----------------
    unsigned int inmask = 0u;
    #pragma unroll
    for (int i = 0; i < 32; ++i)
        inmask |= (s_lab[base + i] == a) ? (1u << i) : 0u;

    #pragma unroll 1
    for (int pass = 0; pass < 2; ++pass) {
        unsigned al = pass ? ~inmask : inmask;
        uint32_t best; int bi;
        scan32(u, al, best, bi);
        int it = 0;
        #pragma unroll 1
        for (; it < RK; ++it) {
            const uint32_t m = __reduce_max_sync(0xffffffffu, best);
            if (m == 0u) break;                      // warp exhausted
            const unsigned msk = __ballot_sync(0xffffffffu, best == m);
            const int src = __ffs(msk) - 1;
            const int widx = __shfl_sync(0xffffffffu, base + bi, src);
            if (lane == 0)
                s_k20[tgt][pass][wt * RK + it] =
                    ((unsigned long long)m << 12) | (unsigned)(4095 - widx);
            if (lane == src) {
                al &= ~(1u << bi);
                scan32(u, al, best, bi);
            }
        }
        for (; it < RK; ++it)
            if (lane == 0) s_k20[tgt][pass][wt * RK + it] = 0ull;
    }
    __syncthreads();

    // ---- warps 0,1 (tgt0) and 4,5 (tgt1) merge the 80-candidate lists -----
    if (wt < 2) {
        const int pass = wt;
        const unsigned long long* keys = s_k20[tgt][pass];
        unsigned long long mk[3];
        mk[0] = keys[lane];
        mk[1] = keys[lane + 32];
        mk[2] = (lane < 16) ? keys[lane + 64] : 0ull;
        unsigned int al = 7u;
        float acc = 0.0f;
        #pragma unroll 1
        for (int it = 0; it < RK; ++it) {
            unsigned long long b = 0ull;
            #pragma unroll
            for (int t = 0; t < 3; ++t)
                if ((al >> t) & 1u) b = (mk[t] > b) ? mk[t] : b;
            unsigned long long key = wmax(b);
            const unsigned int f = (unsigned)(key >> 12);
            if (f == 0u || f == FORD_NEGINF) break;
            acc += s_sim0[tgt][4095 - (int)(key & 0xFFFu)];
            #pragma unroll
            for (int t = 0; t < 3; ++t)
                if (mk[t] == key) al &= ~(1u << t);
        }
        if (lane == 0) s_sum[tgt][pass] = acc;
    }
    __syncthreads();
    if (tid < 2)
        g_scores[blockIdx.x * 2 + tid] = s_sum[tid][0] / s_sum[tid][1];
}

// ---------------- 4. exact top-2048 membership ------------------------------
__global__ void __launch_bounds__(256) select_kernel()
{
    const int j = blockIdx.x;
    const int tid = threadIdx.x;
    __shared__ int sr[8];
    const float sj = g_scores[j];
    int c = 0;
    for (int i = tid; i < NTGT; i += 256) {
        const float si = g_scores[i];
        if (si > sj || (si == sj && i < j)) ++c;
    }
    #pragma unroll
    for (int o = 16; o; o >>= 1) c += __shfl_down_sync(0xffffffffu, c, o);
    if ((tid & 31) == 0) sr[tid >> 5] = c;
    __syncthreads();
    if (tid == 0) {
        int r = 0;
        #pragma unroll
        for (int w = 0; w < 8; ++w) r += sr[w];
        g_sel[j] = (r < TOPN) ? 1 : 0;
    }
}

// ---------------- 5. contrast: fixed shift mm=1 (sim0 = cosine <= 1) -------
__global__ void __launch_bounds__(256) contrast_kernel(const int* __restrict__ slab)
{
    const int j = blockIdx.x;
    const int tid = threadIdx.x;
    __shared__ float s_pA[8];
    __shared__ float s_pM[8];

    if (!g_sel[j]) { if (tid == 0) g_logt[j] = 0.0f; return; }

    const float* row = g_sim0T + (size_t)j * NSRC;
    const int a = g_assigned[j];

    float eA = 0.0f, eM = 0.0f;
    const float itau = 1.0f / TAU;
    for (int i = tid; i < NSRC; i += 256) {
        const float e = expf((row[i] - 1.0f) * itau);   // |sim0|<=1 -> exp>=e^-40
        eA += e;
        if (slab[i] == a) eM += e;
    }
    #pragma unroll
    for (int o = 16; o; o >>= 1) {
        eA += __shfl_down_sync(0xffffffffu, eA, o);
        eM += __shfl_down_sync(0xffffffffu, eM, o);
    }
    if ((tid & 31) == 0) { s_pA[tid >> 5] = eA; s_pM[tid >> 5] = eM; }
    __syncthreads();
    if (tid == 0) {
        float tA = 0.0f, tM = 0.0f;
        #pragma unroll
        for (int w = 0; w < 8; ++w) { tA += s_pA[w]; tM += s_pM[w]; }
        g_logt[j] = logf(tM / tA + EPSL);
    }
}

// ---------------- 6. final deterministic reduction --------------------------
__global__ void __launch_bounds__(256) finalize_kernel(float* out, int out_size)
{
    const int tid = threadIdx.x;
    __shared__ float sr[8];
    float acc = 0.0f;
    for (int i = tid; i < NTGT; i += 256) acc += g_logt[i];
    #pragma unroll
    for (int o = 16; o; o >>= 1) acc += __shfl_down_sync(0xffffffffu, acc, o);
    if ((tid & 31) == 0) sr[tid >> 5] = acc;
    __syncthreads();
    if (tid == 0) {
        float tot = 0.0f;
        #pragma unroll
        for (int w = 0; w < 8; ++w) tot += sr[w];
        out[0] = -(tot / (float)TOPN);
        if (out_size > 1) out[1] = (float)g_nc;
    }
}

// ---------------- host launcher ---------------------------------------------
extern "C" void kernel_launch(void* const* d_in, const int* in_sizes, int n_in,
                              void* d_out, int out_size)
{
    const float* src  = (const float*)d_in[0];
    const int*   slab = (const int*)  d_in[1];
    const float* tgt  = (const float*)d_in[2];
    const float* tgt0 = (const float*)d_in[3];
    const int*   tlab = (const int*)  d_in[4];
    float* out = (float*)d_out;

    cudaFuncSetAttribute(gemm_f16, cudaFuncAttributeMaxDynamicSharedMemorySize,
                         GEMM_SMEM);

    normalize_k<<<dim3(NSRC, 3), 128>>>(src, tgt, tgt0);
    gemm_f16<<<dim3(32, 32), 128, GEMM_SMEM>>>(0, KSPL);  // simT
    gemm_f16<<<dim3(32, 32), 128, GEMM_SMEM>>>(1, KSPL);  // sim0T
    rank_kernel<<<NTGT / 2, 256>>>(slab, tlab);
    select_kernel<<<NTGT, 256>>>();
    contrast_kernel<<<NTGT, 256>>>(slab);
    finalize_kernel<<<1, 256>>>(out, out_size);
}

// round 12
// speedup vs baseline: 1.1373x; 1.1373x over previous
#include <cuda_runtime.h>
#include <cuda_fp16.h>
#include <math.h>
#include <stdint.h>

#define NSRC 4096
#define NTGT 4096
#define DIM  512
#define KSPL 1536          // 3-product fp16 split-K (err ~1e-8, = fp32 baseline)
#define NCLS 64
#define KNN  10
#define RK   20
#define TOPN 2048
#define TAU  0.05f
#define EPSL 1e-6f

#define FORD_NEGINF 0x007FFFFFu

// ---------------- scratch (device globals; allocation-free) ----------------
__device__ __half g_T16 [(size_t)NTGT * KSPL];  // T  split [a0|a0|a1]
__device__ __half g_T016[(size_t)NTGT * KSPL];  // T0 split [a0|a0|a1]
__device__ __half g_S16 [(size_t)NSRC * KSPL];  // S  split [b0|b1|b0] (shared B)
__device__ float g_simT [ (size_t)NTGT * NSRC ];
__device__ float g_sim0T[ (size_t)NTGT * NSRC ];
__device__ int   g_assigned[NTGT];
__device__ float g_scores[NTGT];
__device__ int   g_sel[NTGT];
__device__ float g_logt[NTGT];
__device__ int   g_nc;

// ---------------- helpers ---------------------------------------------------
__device__ __forceinline__ unsigned int ford(float f) {
    unsigned int u = __float_as_uint(f);
    return (u & 0x80000000u) ? ~u : (u | 0x80000000u);
}
__device__ __forceinline__ unsigned long long wmax(unsigned long long k) {
    #pragma unroll
    for (int o = 16; o; o >>= 1) {
        unsigned long long t = __shfl_xor_sync(0xffffffffu, k, o);
        if (t > k) k = t;
    }
    return k;
}
__device__ __forceinline__ uint32_t smem_u32(const void* p) {
    uint32_t a;
    asm("{ .reg .u64 t; cvta.to.shared.u64 t, %1; cvt.u32.u64 %0, t; }" : "=r"(a) : "l"(p));
    return a;
}
__device__ __forceinline__ void ldsm4(uint32_t* r, uint32_t addr) {
    asm volatile("ldmatrix.sync.aligned.m8n8.x4.shared.b16 {%0,%1,%2,%3}, [%4];"
        : "=r"(r[0]), "=r"(r[1]), "=r"(r[2]), "=r"(r[3]) : "r"(addr));
}
__device__ __forceinline__ void ldsm2(uint32_t* r, uint32_t addr) {
    asm volatile("ldmatrix.sync.aligned.m8n8.x2.shared.b16 {%0,%1}, [%2];"
        : "=r"(r[0]), "=r"(r[1]) : "r"(addr));
}
__device__ __forceinline__ void mma16816(float* c, const uint32_t* a, const uint32_t* b) {
    asm volatile("mma.sync.aligned.m16n8k16.row.col.f32.f16.f16.f32 "
        "{%0,%1,%2,%3}, {%4,%5,%6,%7}, {%8,%9}, {%0,%1,%2,%3};"
        : "+f"(c[0]), "+f"(c[1]), "+f"(c[2]), "+f"(c[3])
        : "r"(a[0]), "r"(a[1]), "r"(a[2]), "r"(a[3]), "r"(b[0]), "r"(b[1]));
}
#define CP_A16(dst, src) \
    asm volatile("cp.async.cg.shared.global [%0], [%1], 16;" :: "r"(dst), "l"(src) : "memory")
#define CP_COMMIT() asm volatile("cp.async.commit_group;" ::: "memory")
#define CP_WAIT1()  asm volatile("cp.async.wait_group 1;" ::: "memory")

// 16-element masked argmax over ordered-uint keys (lowest index wins ties)
__device__ __forceinline__ void scan16(const uint32_t* u, unsigned alive,
                                       uint32_t& best, int& bi) {
    best = 0u; bi = 0;
    #pragma unroll
    for (int i = 0; i < 16; ++i) {
        const uint32_t x = ((alive >> i) & 1u) ? u[i] : 0u;
        if (x > best) { best = x; bi = i; }
    }
}

// ---------------- 1. normalize rows + fp16 2-component split emission ------
__global__ void __launch_bounds__(128) normalize_k(
    const float* __restrict__ src, const float* __restrict__ tgt,
    const float* __restrict__ tgt0)
{
    const int r = blockIdx.x;
    const int m = blockIdx.y;
    if (r == 0 && m == 0 && threadIdx.x == 0) g_nc = 0;

    const float* in = (m == 0) ? src : (m == 1) ? tgt : tgt0;

    const float4 v = ((const float4*)(in + (size_t)r * DIM))[threadIdx.x];
    float s = v.x*v.x + v.y*v.y + v.z*v.z + v.w*v.w;
    #pragma unroll
    for (int o = 16; o; o >>= 1) s += __shfl_down_sync(0xffffffffu, s, o);
    __shared__ float ws[4];
    if ((threadIdx.x & 31) == 0) ws[threadIdx.x >> 5] = s;
    __syncthreads();
    const float inv = 1.0f / sqrtf(ws[0] + ws[1] + ws[2] + ws[3]);
    float o4[4] = { v.x * inv, v.y * inv, v.z * inv, v.w * inv };

    __half c0[4], c1[4];
    #pragma unroll
    for (int t = 0; t < 4; ++t) {
        c0[t] = __float2half_rn(o4[t]);
        c1[t] = __float2half_rn(o4[t] - __half2float(c0[t]));
    }
    const int c = threadIdx.x * 4;
    if (m == 0) {            // source S (shared B): [b0 | b1 | b0]
        __half* p = g_S16 + (size_t)r * KSPL;
        #pragma unroll
        for (int t = 0; t < 4; ++t) {
            p[c+t] = c0[t]; p[c+t+512] = c1[t]; p[c+t+1024] = c0[t];
        }
    } else {                 // T / T0: [a0 | a0 | a1]
        __half* p = ((m == 1) ? g_T16 : g_T016) + (size_t)r * KSPL;
        #pragma unroll
        for (int t = 0; t < 4; ++t) {
            p[c+t] = c0[t]; p[c+t+512] = c0[t]; p[c+t+1024] = c1[t];
        }
    }
}

// ---------------- 2. fp16 mma.sync GEMM (R10-validated config) -------------
// 128x128 CTA tile, 8 warps of 64x32, K step 32; 3-stage cp.async pipeline.
#define ST_BYTES 20480
#define GEMM_SMEM (3 * ST_BYTES)   // 61440
__global__ void __launch_bounds__(256) gemm_f16(int which, int K)
{
    extern __shared__ char sm[];
    const __half* __restrict__ A = which ? g_T016 : g_T16;
    const __half* __restrict__ B = g_S16;
    float* __restrict__ C = which ? g_sim0T : g_simT;

    const int tid = threadIdx.x;
    const int bm = blockIdx.y * 128;
    const int bn = blockIdx.x * 128;
    const int lr = tid >> 1;
    const int lh = tid & 1;

    const __half* Ag = A + (size_t)(bm + lr) * K + lh * 16;
    const __half* Bg = B + (size_t)(bn + lr) * K + lh * 16;

    const uint32_t sbase = smem_u32(sm);
    const uint32_t awr = sbase + (uint32_t)lr * 80u + (uint32_t)lh * 32u;
    const uint32_t bwr = awr + 10240u;

    const int w = tid >> 5, lane = tid & 31;
    const int wm = (w >> 2) * 64;
    const int wn = (w & 3) * 32;
    const uint32_t aoff = (uint32_t)(wm + (lane & 15)) * 80u + (uint32_t)(lane >> 4) * 16u;
    const uint32_t boff = 10240u + (uint32_t)(wn + (lane & 7)) * 80u
                        + (uint32_t)((lane >> 3) & 1) * 16u;

    const int NKT = K >> 5;

    #pragma unroll
    for (int t = 0; t < 2; ++t) {
        const uint32_t st = (uint32_t)t * ST_BYTES;
        const __half* as = Ag + t * 32;
        const __half* bs = Bg + t * 32;
        CP_A16(awr + st, as);
        CP_A16(awr + st + 16u, as + 8);
        CP_A16(bwr + st, bs);
        CP_A16(bwr + st + 16u, bs + 8);
        CP_COMMIT();
    }

    float acc[4][4][4];
    #pragma unroll
    for (int mi = 0; mi < 4; ++mi)
        #pragma unroll
        for (int ni = 0; ni < 4; ++ni)
            #pragma unroll
            for (int t = 0; t < 4; ++t) acc[mi][ni][t] = 0.0f;

    #pragma unroll 1
    for (int kt = 0; kt < NKT; ++kt) {
        CP_WAIT1();
        __syncthreads();
        if (kt + 2 < NKT) {
            const uint32_t st = (uint32_t)((kt + 2) % 3) * ST_BYTES;
            const __half* as = Ag + (kt + 2) * 32;
            const __half* bs = Bg + (kt + 2) * 32;
            CP_A16(awr + st, as);
            CP_A16(awr + st + 16u, as + 8);
            CP_A16(bwr + st, bs);
            CP_A16(bwr + st + 16u, bs + 8);
        }
        CP_COMMIT();

        const uint32_t st = (uint32_t)(kt % 3) * ST_BYTES;
        const uint32_t abase = sbase + st + aoff;
        const uint32_t bbase = sbase + st + boff;
        #pragma unroll
        for (int kc = 0; kc < 2; ++kc) {
            uint32_t afr[4][4], bfr[4][2];
            #pragma unroll
            for (int mi = 0; mi < 4; ++mi)
                ldsm4(afr[mi], abase + (uint32_t)mi * (16u * 80u) + (uint32_t)kc * 32u);
            #pragma unroll
            for (int ni = 0; ni < 4; ++ni)
                ldsm2(bfr[ni], bbase + (uint32_t)ni * (8u * 80u) + (uint32_t)kc * 32u);
            #pragma unroll
            for (int mi = 0; mi < 4; ++mi)
                #pragma unroll
                for (int ni = 0; ni < 4; ++ni)
                    mma16816(acc[mi][ni], afr[mi], bfr[ni]);
        }
    }

    const int rbase = bm + wm + (lane >> 2);
    const int cbase = bn + wn + (lane & 3) * 2;
    #pragma unroll
    for (int mi = 0; mi < 4; ++mi) {
        #pragma unroll
        for (int ni = 0; ni < 4; ++ni) {
            const int rr = rbase + mi * 16;
            const int cc = cbase + ni * 8;
            *(float2*)(C + (size_t)rr * NSRC + cc)       = make_float2(acc[mi][ni][0], acc[mi][ni][1]);
            *(float2*)(C + (size_t)(rr + 8) * NSRC + cc) = make_float2(acc[mi][ni][2], acc[mi][ni][3]);
        }
    }
}

// ---------------- 3. per-target selection (R10-validated) ------------------
__global__ void __launch_bounds__(256) rank_kernel(
    const int* __restrict__ slab, const int* __restrict__ tlab)
{
    const int j   = blockIdx.x;
    const int tid = threadIdx.x;
    const int lane = tid & 31;
    const int w    = tid >> 5;

    __shared__ float s_sim0[NSRC];
    __shared__ unsigned char s_lab[NSRC];
    __shared__ unsigned long long s_k10[80];
    __shared__ unsigned long long s_k20[2][160];
    __shared__ int   s_t10[KNN];
    __shared__ int   s_a;
    __shared__ float s_sum[2];

    const float* simrow  = g_simT  + (size_t)j * NSRC;
    const float* sim0row = g_sim0T + (size_t)j * NSRC;

    #pragma unroll
    for (int t = 0; t < 4; ++t) {
        const int i = tid + t * 256;
        ((float4*)s_sim0)[i] = ((const float4*)sim0row)[i];
        int4 lb = ((const int4*)slab)[i];
        uchar4 uu;
        uu.x = (unsigned char)lb.x; uu.y = (unsigned char)lb.y;
        uu.z = (unsigned char)lb.z; uu.w = (unsigned char)lb.w;
        ((uchar4*)s_lab)[i] = uu;
    }

    const int base = w * 512 + lane * 16;
    uint32_t u[16];
    {
        const float4* rp = (const float4*)(simrow + base);
        float4 a = rp[0], b = rp[1], c = rp[2], d = rp[3];
        u[0]=ford(a.x);  u[1]=ford(a.y);  u[2]=ford(a.z);  u[3]=ford(a.w);
        u[4]=ford(b.x);  u[5]=ford(b.y);  u[6]=ford(b.z);  u[7]=ford(b.w);
        u[8]=ford(c.x);  u[9]=ford(c.y);  u[10]=ford(c.z); u[11]=ford(c.w);
        u[12]=ford(d.x); u[13]=ford(d.y); u[14]=ford(d.z); u[15]=ford(d.w);
    }

    {
        unsigned alive = 0xFFFFu;
        uint32_t best; int bi;
        scan16(u, alive, best, bi);
        #pragma unroll 1
        for (int it = 0; it < KNN; ++it) {
            const uint32_t m = __reduce_max_sync(0xffffffffu, best);
            const unsigned msk = __ballot_sync(0xffffffffu, best == m);
            const int src = __ffs(msk) - 1;
            const int widx = __shfl_sync(0xffffffffu, base + bi, src);
            if (lane == 0)
                s_k10[w * KNN + it] =
                    ((unsigned long long)m << 12) | (unsigned)(4095 - widx);
            if (lane == src) {
                alive &= ~(1u << bi);
                scan16(u, alive, best, bi);
            }
        }
    }
    __syncthreads();

    if (w == 0) {
        unsigned long long mk[3];
        mk[0] = s_k10[lane];
        mk[1] = s_k10[lane + 32];
        mk[2] = (lane < 16) ? s_k10[lane + 64] : 0ull;
        unsigned int al = 7u;
        #pragma unroll 1
        for (int it = 0; it < KNN; ++it) {
            unsigned long long b = 0ull;
            #pragma unroll
            for (int t = 0; t < 3; ++t)
                if ((al >> t) & 1u) b = (mk[t] > b) ? mk[t] : b;
            unsigned long long key = wmax(b);
            if (lane == 0) s_t10[it] = 4095 - (int)(key & 0xFFFu);
            #pragma unroll
            for (int t = 0; t < 3; ++t)
                if (mk[t] == key) al &= ~(1u << t);
        }
        if (lane == 0) {
            int cls[KNN];
            #pragma unroll
            for (int k = 0; k < KNN; ++k) cls[k] = s_lab[s_t10[k]];
            int bestc = 1000, bestn = 0;
            #pragma unroll 1
            for (int k = 0; k < KNN; ++k) {
                int n = 0;
                #pragma unroll
                for (int l = 0; l < KNN; ++l) n += (cls[l] == cls[k]);
                if (n > bestn || (n == bestn && cls[k] < bestc)) { bestn = n; bestc = cls[k]; }
            }
            s_a = bestc;
            g_assigned[j] = bestc;
            if (bestc == tlab[j]) atomicAdd(&g_nc, 1);
        }
    }
    __syncthreads();
    const int a = s_a;

    unsigned int inmask = 0u;
    #pragma unroll
    for (int i = 0; i < 16; ++i)
        inmask |= (s_lab[base + i] == a) ? (1u << i) : 0u;

    #pragma unroll 1
    for (int pass = 0; pass < 2; ++pass) {
        unsigned al = pass ? (0xFFFFu & ~inmask) : inmask;
        uint32_t best; int bi;
        scan16(u, al, best, bi);
        int it = 0;
        #pragma unroll 1
        for (; it < RK; ++it) {
            const uint32_t m = __reduce_max_sync(0xffffffffu, best);
            if (m == 0u) break;
            const unsigned msk = __ballot_sync(0xffffffffu, best == m);
            const int src = __ffs(msk) - 1;
            const int widx = __shfl_sync(0xffffffffu, base + bi, src);
            if (lane == 0)
                s_k20[pass][w * RK + it] =
                    ((unsigned long long)m << 12) | (unsigned)(4095 - widx);
            if (lane == src) {
                al &= ~(1u << bi);
                scan16(u, al, best, bi);
            }
        }
        for (; it < RK; ++it)
            if (lane == 0) s_k20[pass][w * RK + it] = 0ull;
    }
    __syncthreads();

    if (w < 2) {
        const unsigned long long* keys = s_k20[w];
        unsigned long long mk[5];
        #pragma unroll
        for (int t = 0; t < 5; ++t) mk[t] = keys[lane + 32 * t];
        unsigned int al = 0x1Fu;
        float acc = 0.0f;
        #pragma unroll 1
        for (int it = 0; it < RK; ++it) {
            unsigned long long b = 0ull;
            #pragma unroll
            for (int t = 0; t < 5; ++t)
                if ((al >> t) & 1u) b = (mk[t] > b) ? mk[t] : b;
            unsigned long long key = wmax(b);
            const unsigned int f = (unsigned)(key >> 12);
            if (f == 0u || f == FORD_NEGINF) break;
            acc += s_sim0[4095 - (int)(key & 0xFFFu)];
            #pragma unroll
            for (int t = 0; t < 5; ++t)
                if (mk[t] == key) al &= ~(1u << t);
        }
        if (lane == 0) s_sum[w] = acc;
    }
    __syncthreads();
    if (tid == 0) g_scores[j] = s_sum[0] / s_sum[1];
}

// ---------------- 4. exact top-2048 membership ------------------------------
__global__ void __launch_bounds__(256) select_kernel()
{
    const int j = blockIdx.x;
    const int tid = threadIdx.x;
    __shared__ int sr[8];
    const float sj = g_scores[j];
    int c = 0;
    for (int i = tid; i < NTGT; i += 256) {
        const float si = g_scores[i];
        if (si > sj || (si == sj && i < j)) ++c;
    }
    #pragma unroll
    for (int o = 16; o; o >>= 1) c += __shfl_down_sync(0xffffffffu, c, o);
    if ((tid & 31) == 0) sr[tid >> 5] = c;
    __syncthreads();
    if (tid == 0) {
        int r = 0;
        #pragma unroll
        for (int w = 0; w < 8; ++w) r += sr[w];
        g_sel[j] = (r < TOPN) ? 1 : 0;
    }
}

// ---------------- 5. contrast: fixed shift (sim0 = cosine <= 1) ------------
__global__ void __launch_bounds__(256) contrast_kernel(const int* __restrict__ slab)
{
    const int j = blockIdx.x;
    const int tid = threadIdx.x;
    __shared__ float s_pA[8];
    __shared__ float s_pM[8];

    if (!g_sel[j]) { if (tid == 0) g_logt[j] = 0.0f; return; }

    const float* row = g_sim0T + (size_t)j * NSRC;
    const int a = g_assigned[j];

    float eA = 0.0f, eM = 0.0f;
    const float itau = 1.0f / TAU;
    for (int i = tid; i < NSRC; i += 256) {
        const float e = expf((row[i] - 1.0f) * itau);   // |sim0|<=1 -> exp>=e^-40
        eA += e;
        if (slab[i] == a) eM += e;
    }
    #pragma unroll
    for (int o = 16; o; o >>= 1) {
        eA += __shfl_down_sync(0xffffffffu, eA, o);
        eM += __shfl_down_sync(0xffffffffu, eM, o);
    }
    if ((tid & 31) == 0) { s_pA[tid >> 5] = eA; s_pM[tid >> 5] = eM; }
    __syncthreads();
    if (tid == 0) {
        float tA = 0.0f, tM = 0.0f;
        #pragma unroll
        for (int w = 0; w < 8; ++w) { tA += s_pA[w]; tM += s_pM[w]; }
        g_logt[j] = logf(tM / tA + EPSL);
    }
}

// ---------------- 6. final deterministic reduction --------------------------
__global__ void __launch_bounds__(256) finalize_kernel(float* out, int out_size)
{
    const int tid = threadIdx.x;
    __shared__ float sr[8];
    float acc = 0.0f;
    for (int i = tid; i < NTGT; i += 256) acc += g_logt[i];
    #pragma unroll
    for (int o = 16; o; o >>= 1) acc += __shfl_down_sync(0xffffffffu, acc, o);
    if ((tid & 31) == 0) sr[tid >> 5] = acc;
    __syncthreads();
    if (tid == 0) {
        float tot = 0.0f;
        #pragma unroll
        for (int w = 0; w < 8; ++w) tot += sr[w];
        out[0] = -(tot / (float)TOPN);
        if (out_size > 1) out[1] = (float)g_nc;
    }
}

// ---------------- host launcher ---------------------------------------------
extern "C" void kernel_launch(void* const* d_in, const int* in_sizes, int n_in,
                              void* d_out, int out_size)
{
    const float* src  = (const float*)d_in[0];
    const int*   slab = (const int*)  d_in[1];
    const float* tgt  = (const float*)d_in[2];
    const float* tgt0 = (const float*)d_in[3];
    const int*   tlab = (const int*)  d_in[4];
    float* out = (float*)d_out;

    cudaFuncSetAttribute(gemm_f16, cudaFuncAttributeMaxDynamicSharedMemorySize,
                         GEMM_SMEM);

    normalize_k<<<dim3(NSRC, 3), 128>>>(src, tgt, tgt0);
    gemm_f16<<<dim3(32, 32), 256, GEMM_SMEM>>>(0, KSPL);  // simT
    gemm_f16<<<dim3(32, 32), 256, GEMM_SMEM>>>(1, KSPL);  // sim0T
    rank_kernel<<<NTGT, 256>>>(slab, tlab);
    select_kernel<<<NTGT, 256>>>();
    contrast_kernel<<<NTGT, 256>>>(slab);
    finalize_kernel<<<1, 256>>>(out, out_size);
}

// round 14
// speedup vs baseline: 1.2540x; 1.1027x over previous
#include <cuda_runtime.h>
#include <cuda_fp16.h>
#include <math.h>
#include <stdint.h>

#define NSRC 4096
#define NTGT 4096
#define DIM  512
#define KSPL 1536          // 3-product fp16 split-K (err ~1e-8, = fp32 baseline)
#define NCLS 64
#define KNN  10
#define RK   20
#define TOPN 2048
#define TAU  0.05f
#define EPSL 1e-6f

#define FORD_NEGINF 0x007FFFFFu

// ---------------- scratch (device globals; allocation-free) ----------------
__device__ __half g_T16 [(size_t)NTGT * KSPL];  // T  split [a0|a0|a1]
__device__ __half g_T016[(size_t)NTGT * KSPL];  // T0 split [a0|a0|a1]
__device__ __half g_S16 [(size_t)NSRC * KSPL];  // S  split [b0|b1|b0] (shared B)
__device__ float g_simT [ (size_t)NTGT * NSRC ];
__device__ float g_sim0T[ (size_t)NTGT * NSRC ];
__device__ int   g_assigned[NTGT];
__device__ float g_scores[NTGT];
__device__ int   g_sel[NTGT];
__device__ float g_logt[NTGT];
__device__ int   g_nc;

// ---------------- helpers ---------------------------------------------------
__device__ __forceinline__ unsigned int ford(float f) {
    unsigned int u = __float_as_uint(f);
    return (u & 0x80000000u) ? ~u : (u | 0x80000000u);
}
__device__ __forceinline__ unsigned long long wmax(unsigned long long k) {
    #pragma unroll
    for (int o = 16; o; o >>= 1) {
        unsigned long long t = __shfl_xor_sync(0xffffffffu, k, o);
        if (t > k) k = t;
    }
    return k;
}
__device__ __forceinline__ uint32_t smem_u32(const void* p) {
    uint32_t a;
    asm("{ .reg .u64 t; cvta.to.shared.u64 t, %1; cvt.u32.u64 %0, t; }" : "=r"(a) : "l"(p));
    return a;
}
__device__ __forceinline__ void ldsm4(uint32_t* r, uint32_t addr) {
    asm volatile("ldmatrix.sync.aligned.m8n8.x4.shared.b16 {%0,%1,%2,%3}, [%4];"
        : "=r"(r[0]), "=r"(r[1]), "=r"(r[2]), "=r"(r[3]) : "r"(addr));
}
__device__ __forceinline__ void ldsm2(uint32_t* r, uint32_t addr) {
    asm volatile("ldmatrix.sync.aligned.m8n8.x2.shared.b16 {%0,%1}, [%2];"
        : "=r"(r[0]), "=r"(r[1]) : "r"(addr));
}
__device__ __forceinline__ void mma16816(float* c, const uint32_t* a, const uint32_t* b) {
    asm volatile("mma.sync.aligned.m16n8k16.row.col.f32.f16.f16.f32 "
        "{%0,%1,%2,%3}, {%4,%5,%6,%7}, {%8,%9}, {%0,%1,%2,%3};"
        : "+f"(c[0]), "+f"(c[1]), "+f"(c[2]), "+f"(c[3])
        : "r"(a[0]), "r"(a[1]), "r"(a[2]), "r"(a[3]), "r"(b[0]), "r"(b[1]));
}
#define CP_A16(dst, src) \
    asm volatile("cp.async.cg.shared.global [%0], [%1], 16;" :: "r"(dst), "l"(src) : "memory")
#define CP_COMMIT() asm volatile("cp.async.commit_group;" ::: "memory")
#define CP_WAIT1()  asm volatile("cp.async.wait_group 1;" ::: "memory")

// ---------------- 1. normalize rows + fp16 2-component split emission ------
__global__ void __launch_bounds__(128) normalize_k(
    const float* __restrict__ src, const float* __restrict__ tgt,
    const float* __restrict__ tgt0)
{
    const int r = blockIdx.x;
    const int m = blockIdx.y;
    if (r == 0 && m == 0 && threadIdx.x == 0) g_nc = 0;

    const float* in = (m == 0) ? src : (m == 1) ? tgt : tgt0;

    const float4 v = ((const float4*)(in + (size_t)r * DIM))[threadIdx.x];
    float s = v.x*v.x + v.y*v.y + v.z*v.z + v.w*v.w;
    #pragma unroll
    for (int o = 16; o; o >>= 1) s += __shfl_down_sync(0xffffffffu, s, o);
    __shared__ float ws[4];
    if ((threadIdx.x & 31) == 0) ws[threadIdx.x >> 5] = s;
    __syncthreads();
    const float inv = 1.0f / sqrtf(ws[0] + ws[1] + ws[2] + ws[3]);
    float o4[4] = { v.x * inv, v.y * inv, v.z * inv, v.w * inv };

    __half c0[4], c1[4];
    #pragma unroll
    for (int t = 0; t < 4; ++t) {
        c0[t] = __float2half_rn(o4[t]);
        c1[t] = __float2half_rn(o4[t] - __half2float(c0[t]));
    }
    const int c = threadIdx.x * 4;
    if (m == 0) {            // source S (shared B): [b0 | b1 | b0]
        __half* p = g_S16 + (size_t)r * KSPL;
        #pragma unroll
        for (int t = 0; t < 4; ++t) {
            p[c+t] = c0[t]; p[c+t+512] = c1[t]; p[c+t+1024] = c0[t];
        }
    } else {                 // T / T0: [a0 | a0 | a1]
        __half* p = ((m == 1) ? g_T16 : g_T016) + (size_t)r * KSPL;
        #pragma unroll
        for (int t = 0; t < 4; ++t) {
            p[c+t] = c0[t]; p[c+t+512] = c0[t]; p[c+t+1024] = c1[t];
        }
    }
}

// ---------------- 2. fp16 mma.sync GEMM (R10-validated config) -------------
#define ST_BYTES 20480
#define GEMM_SMEM (3 * ST_BYTES)   // 61440
__global__ void __launch_bounds__(256) gemm_f16(int which, int K)
{
    extern __shared__ char sm[];
    const __half* __restrict__ A = which ? g_T016 : g_T16;
    const __half* __restrict__ B = g_S16;
    float* __restrict__ C = which ? g_sim0T : g_simT;

    const int tid = threadIdx.x;
    const int bm = blockIdx.y * 128;
    const int bn = blockIdx.x * 128;
    const int lr = tid >> 1;
    const int lh = tid & 1;

    const __half* Ag = A + (size_t)(bm + lr) * K + lh * 16;
    const __half* Bg = B + (size_t)(bn + lr) * K + lh * 16;

    const uint32_t sbase = smem_u32(sm);
    const uint32_t awr = sbase + (uint32_t)lr * 80u + (uint32_t)lh * 32u;
    const uint32_t bwr = awr + 10240u;

    const int w = tid >> 5, lane = tid & 31;
    const int wm = (w >> 2) * 64;
    const int wn = (w & 3) * 32;
    const uint32_t aoff = (uint32_t)(wm + (lane & 15)) * 80u + (uint32_t)(lane >> 4) * 16u;
    const uint32_t boff = 10240u + (uint32_t)(wn + (lane & 7)) * 80u
                        + (uint32_t)((lane >> 3) & 1) * 16u;

    const int NKT = K >> 5;

    #pragma unroll
    for (int t = 0; t < 2; ++t) {
        const uint32_t st = (uint32_t)t * ST_BYTES;
        const __half* as = Ag + t * 32;
        const __half* bs = Bg + t * 32;
        CP_A16(awr + st, as);
        CP_A16(awr + st + 16u, as + 8);
        CP_A16(bwr + st, bs);
        CP_A16(bwr + st + 16u, bs + 8);
        CP_COMMIT();
    }

    float acc[4][4][4];
    #pragma unroll
    for (int mi = 0; mi < 4; ++mi)
        #pragma unroll
        for (int ni = 0; ni < 4; ++ni)
            #pragma unroll
            for (int t = 0; t < 4; ++t) acc[mi][ni][t] = 0.0f;

    #pragma unroll 1
    for (int kt = 0; kt < NKT; ++kt) {
        CP_WAIT1();
        __syncthreads();
        if (kt + 2 < NKT) {
            const uint32_t st = (uint32_t)((kt + 2) % 3) * ST_BYTES;
            const __half* as = Ag + (kt + 2) * 32;
            const __half* bs = Bg + (kt + 2) * 32;
            CP_A16(awr + st, as);
            CP_A16(awr + st + 16u, as + 8);
            CP_A16(bwr + st, bs);
            CP_A16(bwr + st + 16u, bs + 8);
        }
        CP_COMMIT();

        const uint32_t st = (uint32_t)(kt % 3) * ST_BYTES;
        const uint32_t abase = sbase + st + aoff;
        const uint32_t bbase = sbase + st + boff;
        #pragma unroll
        for (int kc = 0; kc < 2; ++kc) {
            uint32_t afr[4][4], bfr[4][2];
            #pragma unroll
            for (int mi = 0; mi < 4; ++mi)
                ldsm4(afr[mi], abase + (uint32_t)mi * (16u * 80u) + (uint32_t)kc * 32u);
            #pragma unroll
            for (int ni = 0; ni < 4; ++ni)
                ldsm2(bfr[ni], bbase + (uint32_t)ni * (8u * 80u) + (uint32_t)kc * 32u);
            #pragma unroll
            for (int mi = 0; mi < 4; ++mi)
                #pragma unroll
                for (int ni = 0; ni < 4; ++ni)
                    mma16816(acc[mi][ni], afr[mi], bfr[ni]);
        }
    }

    const int rbase = bm + wm + (lane >> 2);
    const int cbase = bn + wn + (lane & 3) * 2;
    #pragma unroll
    for (int mi = 0; mi < 4; ++mi) {
        #pragma unroll
        for (int ni = 0; ni < 4; ++ni) {
            const int rr = rbase + mi * 16;
            const int cc = cbase + ni * 8;
            *(float2*)(C + (size_t)rr * NSRC + cc)       = make_float2(acc[mi][ni][0], acc[mi][ni][1]);
            *(float2*)(C + (size_t)(rr + 8) * NSRC + cc) = make_float2(acc[mi][ni][2], acc[mi][ni][3]);
        }
    }
}

// ---------------- 3. selection: per-thread pre-sorted keys -----------------
// Each thread bitonic-sorts its 16 items once as u64 (ford<<4 | (15-i)) ->
// exact "val desc, idx asc" order. Sorted fords live in smem (stride 17,
// conflict-free); the thread's current best among alive items is the lowest
// set bit of a 16-bit remaining-mask. Per iteration: ffs + LDS + redux +
// ballot; the winning lane writes the candidate key and clears its low bit.
__global__ void __launch_bounds__(256) rank_kernel(
    const int* __restrict__ slab, const int* __restrict__ tlab)
{
    const int j   = blockIdx.x;
    const int tid = threadIdx.x;
    const int lane = tid & 31;
    const int w    = tid >> 5;

    __shared__ uint32_t s_ford[256 * 17];
    __shared__ unsigned char s_lab[NSRC];
    __shared__ unsigned long long s_k10[80];
    __shared__ unsigned long long s_k20[2][160];
    __shared__ int   s_t10[KNN];
    __shared__ int   s_a;
    __shared__ float s_sum[2];

    const float* simrow = g_simT + (size_t)j * NSRC;

    #pragma unroll
    for (int t = 0; t < 4; ++t) {
        const int i = tid + t * 256;
        int4 lb = ((const int4*)slab)[i];
        uchar4 uu;
        uu.x = (unsigned char)lb.x; uu.y = (unsigned char)lb.y;
        uu.z = (unsigned char)lb.z; uu.w = (unsigned char)lb.w;
        ((uchar4*)s_lab)[i] = uu;
    }

    const int base = w * 512 + lane * 16;

    // ---- load 16 sims, build u64 sort keys, bitonic sort descending -------
    unsigned long long s[16];
    {
        const float4* rp = (const float4*)(simrow + base);
        #pragma unroll
        for (int q = 0; q < 4; ++q) {
            float4 vv = rp[q];
            s[q*4+0] = ((unsigned long long)ford(vv.x) << 4) | (unsigned)(15 - (q*4+0));
            s[q*4+1] = ((unsigned long long)ford(vv.y) << 4) | (unsigned)(15 - (q*4+1));
            s[q*4+2] = ((unsigned long long)ford(vv.z) << 4) | (unsigned)(15 - (q*4+2));
            s[q*4+3] = ((unsigned long long)ford(vv.w) << 4) | (unsigned)(15 - (q*4+3));
        }
    }
    #pragma unroll
    for (int k = 2; k <= 16; k <<= 1) {
        #pragma unroll
        for (int j2 = k >> 1; j2 > 0; j2 >>= 1) {
            #pragma unroll
            for (int i = 0; i < 16; ++i) {
                const int l = i ^ j2;
                if (l > i) {
                    const bool asc = (i & k) != 0;
                    const bool sw = asc ? (s[i] > s[l]) : (s[i] < s[l]);
                    if (sw) { unsigned long long t = s[i]; s[i] = s[l]; s[l] = t; }
                }
            }
        }
    }

    // ---- publish sorted fords to smem; keep orig-idx nibbles in a u64 -----
    const int fbase = tid * 17;
    unsigned long long idxpack = 0ull;
    #pragma unroll
    for (int p = 0; p < 16; ++p) {
        s_ford[fbase + p] = (uint32_t)(s[p] >> 4);
        idxpack |= (unsigned long long)(15 - (int)(s[p] & 15ull)) << (4 * p);
    }
    __syncthreads();   // also covers s_lab

    // ---- top-10 overall ---------------------------------------------------
    {
        unsigned rem = 0xFFFFu;
        #pragma unroll 1
        for (int it = 0; it < KNN; ++it) {
            const int p = __ffs(rem) - 1;
            const uint32_t best = s_ford[fbase + p];
            const uint32_t m = __reduce_max_sync(0xffffffffu, best);
            const unsigned msk = __ballot_sync(0xffffffffu, best == m);
            if (lane == __ffs(msk) - 1) {
                const int orig = (int)((idxpack >> (4 * p)) & 15ull);
                s_k10[w * KNN + it] =
                    ((unsigned long long)m << 12) | (unsigned)(4095 - (base + orig));
                rem &= rem - 1;
            }
        }
    }
    __syncthreads();

    // ---- warp 0: merge 80 candidates -> global top-10, assign label -------
    if (w == 0) {
        unsigned long long mk[3];
        mk[0] = s_k10[lane];
        mk[1] = s_k10[lane + 32];
        mk[2] = (lane < 16) ? s_k10[lane + 64] : 0ull;
        unsigned int al = 7u;
        #pragma unroll 1
        for (int it = 0; it < KNN; ++it) {
            unsigned long long b = 0ull;
            #pragma unroll
            for (int t = 0; t < 3; ++t)
                if ((al >> t) & 1u) b = (mk[t] > b) ? mk[t] : b;
            unsigned long long key = wmax(b);
            if (lane == 0) s_t10[it] = 4095 - (int)(key & 0xFFFu);
            #pragma unroll
            for (int t = 0; t < 3; ++t)
                if (mk[t] == key) al &= ~(1u << t);
        }
        if (lane == 0) {
            int cls[KNN];
            #pragma unroll
            for (int k = 0; k < KNN; ++k) cls[k] = s_lab[s_t10[k]];
            int bestc = 1000, bestn = 0;
            #pragma unroll 1
            for (int k = 0; k < KNN; ++k) {
                int n = 0;
                #pragma unroll
                for (int l = 0; l < KNN; ++l) n += (cls[l] == cls[k]);
                if (n > bestn || (n == bestn && cls[k] < bestc)) { bestn = n; bestc = cls[k]; }
            }
            s_a = bestc;
            g_assigned[j] = bestc;
            if (bestc == tlab[j]) atomicAdd(&g_nc, 1);
        }
    }
    __syncthreads();
    const int a = s_a;

    // ---- class membership mapped through the sorted permutation -----------
    unsigned maskS = 0u;
    #pragma unroll
    for (int p = 0; p < 16; ++p) {
        const int orig = (int)((idxpack >> (4 * p)) & 15ull);
        maskS |= (s_lab[base + orig] == a) ? (1u << p) : 0u;
    }

    // ---- masked top-20 (in-class / out-of-class) --------------------------
    #pragma unroll 1
    for (int pass = 0; pass < 2; ++pass) {
        unsigned rem = pass ? (0xFFFFu & ~maskS) : maskS;
        int it = 0;
        #pragma unroll 1
        for (; it < RK; ++it) {
            const int p = __ffs(rem | 0x10000u) - 1;        // p=16 pad slot if empty
            const uint32_t best = rem ? s_ford[fbase + p] : 0u;
            const uint32_t m = __reduce_max_sync(0xffffffffu, best);
            if (m == 0u) break;                             // warp exhausted
            const unsigned msk = __ballot_sync(0xffffffffu, best == m);
            if (lane == __ffs(msk) - 1) {
                const int orig = (int)((idxpack >> (4 * p)) & 15ull);
                s_k20[pass][w * RK + it] =
                    ((unsigned long long)m << 12) | (unsigned)(4095 - (base + orig));
                rem &= rem - 1;
            }
        }
        for (; it < RK; ++it)
            if (lane == 0) s_k20[pass][w * RK + it] = 0ull;
    }
    __syncthreads();

    // ---- warps 0,1 merge the two 160-candidate lists; gather sim0 via LDG -
    if (w < 2) {
        const float* sim0row = g_sim0T + (size_t)j * NSRC;
        const unsigned long long* keys = s_k20[w];
        unsigned long long mk[5];
        #pragma unroll
        for (int t = 0; t < 5; ++t) mk[t] = keys[lane + 32 * t];
        unsigned int al = 0x1Fu;
        float acc = 0.0f;
        #pragma unroll 1
        for (int it = 0; it < RK; ++it) {
            unsigned long long b = 0ull;
            #pragma unroll
            for (int t = 0; t < 5; ++t)
                if ((al >> t) & 1u) b = (mk[t] > b) ? mk[t] : b;
            unsigned long long key = wmax(b);
            const unsigned int f = (unsigned)(key >> 12);
            if (f == 0u || f == FORD_NEGINF) break;
            acc += __ldg(sim0row + (4095 - (int)(key & 0xFFFu)));
            #pragma unroll
            for (int t = 0; t < 5; ++t)
                if (mk[t] == key) al &= ~(1u << t);
        }
        if (lane == 0) s_sum[w] = acc;
    }
    __syncthreads();
    if (tid == 0) g_scores[j] = s_sum[0] / s_sum[1];
}

// ---------------- 4. exact top-2048 membership ------------------------------
__global__ void __launch_bounds__(256) select_kernel()
{
    const int j = blockIdx.x;
    const int tid = threadIdx.x;
    __shared__ int sr[8];
    const float sj = g_scores[j];
    int c = 0;
    for (int i = tid; i < NTGT; i += 256) {
        const float si = g_scores[i];
        if (si > sj || (si == sj && i < j)) ++c;
    }
    #pragma unroll
    for (int o = 16; o; o >>= 1) c += __shfl_down_sync(0xffffffffu, c, o);
    if ((tid & 31) == 0) sr[tid >> 5] = c;
    __syncthreads();
    if (tid == 0) {
        int r = 0;
        #pragma unroll
        for (int w = 0; w < 8; ++w) r += sr[w];
        g_sel[j] = (r < TOPN) ? 1 : 0;
    }
}

// ---------------- 5. contrast: fixed shift (sim0 = cosine <= 1) ------------
__global__ void __launch_bounds__(256) contrast_kernel(const int* __restrict__ slab)
{
    const int j = blockIdx.x;
    const int tid = threadIdx.x;
    __shared__ float s_pA[8];
    __shared__ float s_pM[8];

    if (!g_sel[j]) { if (tid == 0) g_logt[j] = 0.0f; return; }

    const float* row = g_sim0T + (size_t)j * NSRC;
    const int a = g_assigned[j];

    float eA = 0.0f, eM = 0.0f;
    const float itau = 1.0f / TAU;
    for (int i = tid; i < NSRC; i += 256) {
        const float e = expf((row[i] - 1.0f) * itau);   // |sim0|<=1 -> exp>=e^-40
        eA += e;
        if (slab[i] == a) eM += e;
    }
    #pragma unroll
    for (int o = 16; o; o >>= 1) {
        eA += __shfl_down_sync(0xffffffffu, eA, o);
        eM += __shfl_down_sync(0xffffffffu, eM, o);
    }
    if ((tid & 31) == 0) { s_pA[tid >> 5] = eA; s_pM[tid >> 5] = eM; }
    __syncthreads();
    if (tid == 0) {
        float tA = 0.0f, tM = 0.0f;
        #pragma unroll
        for (int w = 0; w < 8; ++w) { tA += s_pA[w]; tM += s_pM[w]; }
        g_logt[j] = logf(tM / tA + EPSL);
    }
}

// ---------------- 6. final deterministic reduction --------------------------
__global__ void __launch_bounds__(256) finalize_kernel(float* out, int out_size)
{
    const int tid = threadIdx.x;
    __shared__ float sr[8];
    float acc = 0.0f;
    for (int i = tid; i < NTGT; i += 256) acc += g_logt[i];
    #pragma unroll
    for (int o = 16; o; o >>= 1) acc += __shfl_down_sync(0xffffffffu, acc, o);
    if ((tid & 31) == 0) sr[tid >> 5] = acc;
    __syncthreads();
    if (tid == 0) {
        float tot = 0.0f;
        #pragma unroll
        for (int w = 0; w < 8; ++w) tot += sr[w];
        out[0] = -(tot / (float)TOPN);
        if (out_size > 1) out[1] = (float)g_nc;
    }
}

// ---------------- host launcher ---------------------------------------------
extern "C" void kernel_launch(void* const* d_in, const int* in_sizes, int n_in,
                              void* d_out, int out_size)
{
    const float* src  = (const float*)d_in[0];
    const int*   slab = (const int*)  d_in[1];
    const float* tgt  = (const float*)d_in[2];
    const float* tgt0 = (const float*)d_in[3];
    const int*   tlab = (const int*)  d_in[4];
    float* out = (float*)d_out;

    cudaFuncSetAttribute(gemm_f16, cudaFuncAttributeMaxDynamicSharedMemorySize,
                         GEMM_SMEM);

    normalize_k<<<dim3(NSRC, 3), 128>>>(src, tgt, tgt0);
    gemm_f16<<<dim3(32, 32), 256, GEMM_SMEM>>>(0, KSPL);  // simT
    gemm_f16<<<dim3(32, 32), 256, GEMM_SMEM>>>(1, KSPL);  // sim0T
    rank_kernel<<<NTGT, 256>>>(slab, tlab);
    select_kernel<<<NTGT, 256>>>();
    contrast_kernel<<<NTGT, 256>>>(slab);
    finalize_kernel<<<1, 256>>>(out, out_size);
}

// round 15
// speedup vs baseline: 1.3168x; 1.0501x over previous
#include <cuda_runtime.h>
#include <cuda_fp16.h>
#include <math.h>
#include <stdint.h>

#define NSRC 4096
#define NTGT 4096
#define DIM  512
#define KSPL 1536          // 3-product fp16 split-K (err ~1e-8, = fp32 baseline)
#define NCLS 64
#define KNN  10
#define RK   20
#define TOPN 2048
#define TAU  0.05f
#define EPSL 1e-6f

#define FORD_NEGINF 0x007FFFFFu

// ---------------- scratch (device globals; allocation-free) ----------------
__device__ __half g_T16 [(size_t)NTGT * KSPL];  // T  split [a0|a0|a1]
__device__ __half g_T016[(size_t)NTGT * KSPL];  // T0 split [a0|a0|a1]
__device__ __half g_S16 [(size_t)NSRC * KSPL];  // S  split [b0|b1|b0] (shared B)
__device__ float g_simT [ (size_t)NTGT * NSRC ];
__device__ float g_sim0T[ (size_t)NTGT * NSRC ];
__device__ int   g_assigned[NTGT];
__device__ float g_scores[NTGT];
__device__ int   g_sel[NTGT];
__device__ float g_logt[NTGT];
__device__ int   g_nc;

// ---------------- helpers ---------------------------------------------------
__device__ __forceinline__ unsigned int ford(float f) {
    unsigned int u = __float_as_uint(f);
    return (u & 0x80000000u) ? ~u : (u | 0x80000000u);
}
__device__ __forceinline__ unsigned long long wmax(unsigned long long k) {
    #pragma unroll
    for (int o = 16; o; o >>= 1) {
        unsigned long long t = __shfl_xor_sync(0xffffffffu, k, o);
        if (t > k) k = t;
    }
    return k;
}
__device__ __forceinline__ uint32_t smem_u32(const void* p) {
    uint32_t a;
    asm("{ .reg .u64 t; cvta.to.shared.u64 t, %1; cvt.u32.u64 %0, t; }" : "=r"(a) : "l"(p));
    return a;
}
__device__ __forceinline__ void ldsm4(uint32_t* r, uint32_t addr) {
    asm volatile("ldmatrix.sync.aligned.m8n8.x4.shared.b16 {%0,%1,%2,%3}, [%4];"
        : "=r"(r[0]), "=r"(r[1]), "=r"(r[2]), "=r"(r[3]) : "r"(addr));
}
__device__ __forceinline__ void ldsm2(uint32_t* r, uint32_t addr) {
    asm volatile("ldmatrix.sync.aligned.m8n8.x2.shared.b16 {%0,%1}, [%2];"
        : "=r"(r[0]), "=r"(r[1]) : "r"(addr));
}
__device__ __forceinline__ void mma16816(float* c, const uint32_t* a, const uint32_t* b) {
    asm volatile("mma.sync.aligned.m16n8k16.row.col.f32.f16.f16.f32 "
        "{%0,%1,%2,%3}, {%4,%5,%6,%7}, {%8,%9}, {%0,%1,%2,%3};"
        : "+f"(c[0]), "+f"(c[1]), "+f"(c[2]), "+f"(c[3])
        : "r"(a[0]), "r"(a[1]), "r"(a[2]), "r"(a[3]), "r"(b[0]), "r"(b[1]));
}
#define CP_A16(dst, src) \
    asm volatile("cp.async.cg.shared.global [%0], [%1], 16;" :: "r"(dst), "l"(src) : "memory")
#define CP_COMMIT() asm volatile("cp.async.commit_group;" ::: "memory")
#define CP_WAIT1()  asm volatile("cp.async.wait_group 1;" ::: "memory")

// ---------------- 1. normalize rows + fp16 2-component split emission ------
__global__ void __launch_bounds__(128) normalize_k(
    const float* __restrict__ src, const float* __restrict__ tgt,
    const float* __restrict__ tgt0)
{
    const int r = blockIdx.x;
    const int m = blockIdx.y;
    if (r == 0 && m == 0 && threadIdx.x == 0) g_nc = 0;

    const float* in = (m == 0) ? src : (m == 1) ? tgt : tgt0;

    const float4 v = ((const float4*)(in + (size_t)r * DIM))[threadIdx.x];
    float s = v.x*v.x + v.y*v.y + v.z*v.z + v.w*v.w;
    #pragma unroll
    for (int o = 16; o; o >>= 1) s += __shfl_down_sync(0xffffffffu, s, o);
    __shared__ float ws[4];
    if ((threadIdx.x & 31) == 0) ws[threadIdx.x >> 5] = s;
    __syncthreads();
    const float inv = 1.0f / sqrtf(ws[0] + ws[1] + ws[2] + ws[3]);
    float o4[4] = { v.x * inv, v.y * inv, v.z * inv, v.w * inv };

    __half c0[4], c1[4];
    #pragma unroll
    for (int t = 0; t < 4; ++t) {
        c0[t] = __float2half_rn(o4[t]);
        c1[t] = __float2half_rn(o4[t] - __half2float(c0[t]));
    }
    const int c = threadIdx.x * 4;
    if (m == 0) {            // source S (shared B): [b0 | b1 | b0]
        __half* p = g_S16 + (size_t)r * KSPL;
        #pragma unroll
        for (int t = 0; t < 4; ++t) {
            p[c+t] = c0[t]; p[c+t+512] = c1[t]; p[c+t+1024] = c0[t];
        }
    } else {                 // T / T0: [a0 | a0 | a1]
        __half* p = ((m == 1) ? g_T16 : g_T016) + (size_t)r * KSPL;
        #pragma unroll
        for (int t = 0; t < 4; ++t) {
            p[c+t] = c0[t]; p[c+t+512] = c0[t]; p[c+t+1024] = c1[t];
        }
    }
}

// ---------------- 2. fp16 mma.sync GEMM (R10 config; both C's in one grid) -
#define ST_BYTES 20480
#define GEMM_SMEM (3 * ST_BYTES)   // 61440
__global__ void __launch_bounds__(256) gemm_f16(int K)
{
    extern __shared__ char sm[];
    const int which = blockIdx.z;
    const __half* __restrict__ A = which ? g_T016 : g_T16;
    const __half* __restrict__ B = g_S16;
    float* __restrict__ C = which ? g_sim0T : g_simT;

    const int tid = threadIdx.x;
    const int bm = blockIdx.y * 128;
    const int bn = blockIdx.x * 128;
    const int lr = tid >> 1;
    const int lh = tid & 1;

    const __half* Ag = A + (size_t)(bm + lr) * K + lh * 16;
    const __half* Bg = B + (size_t)(bn + lr) * K + lh * 16;

    const uint32_t sbase = smem_u32(sm);
    const uint32_t awr = sbase + (uint32_t)lr * 80u + (uint32_t)lh * 32u;
    const uint32_t bwr = awr + 10240u;

    const int w = tid >> 5, lane = tid & 31;
    const int wm = (w >> 2) * 64;
    const int wn = (w & 3) * 32;
    const uint32_t aoff = (uint32_t)(wm + (lane & 15)) * 80u + (uint32_t)(lane >> 4) * 16u;
    const uint32_t boff = 10240u + (uint32_t)(wn + (lane & 7)) * 80u
                        + (uint32_t)((lane >> 3) & 1) * 16u;

    const int NKT = K >> 5;

    #pragma unroll
    for (int t = 0; t < 2; ++t) {
        const uint32_t st = (uint32_t)t * ST_BYTES;
        const __half* as = Ag + t * 32;
        const __half* bs = Bg + t * 32;
        CP_A16(awr + st, as);
        CP_A16(awr + st + 16u, as + 8);
        CP_A16(bwr + st, bs);
        CP_A16(bwr + st + 16u, bs + 8);
        CP_COMMIT();
    }

    float acc[4][4][4];
    #pragma unroll
    for (int mi = 0; mi < 4; ++mi)
        #pragma unroll
        for (int ni = 0; ni < 4; ++ni)
            #pragma unroll
            for (int t = 0; t < 4; ++t) acc[mi][ni][t] = 0.0f;

    #pragma unroll 1
    for (int kt = 0; kt < NKT; ++kt) {
        CP_WAIT1();
        __syncthreads();
        if (kt + 2 < NKT) {
            const uint32_t st = (uint32_t)((kt + 2) % 3) * ST_BYTES;
            const __half* as = Ag + (kt + 2) * 32;
            const __half* bs = Bg + (kt + 2) * 32;
            CP_A16(awr + st, as);
            CP_A16(awr + st + 16u, as + 8);
            CP_A16(bwr + st, bs);
            CP_A16(bwr + st + 16u, bs + 8);
        }
        CP_COMMIT();

        const uint32_t st = (uint32_t)(kt % 3) * ST_BYTES;
        const uint32_t abase = sbase + st + aoff;
        const uint32_t bbase = sbase + st + boff;
        #pragma unroll
        for (int kc = 0; kc < 2; ++kc) {
            uint32_t afr[4][4], bfr[4][2];
            #pragma unroll
            for (int mi = 0; mi < 4; ++mi)
                ldsm4(afr[mi], abase + (uint32_t)mi * (16u * 80u) + (uint32_t)kc * 32u);
            #pragma unroll
            for (int ni = 0; ni < 4; ++ni)
                ldsm2(bfr[ni], bbase + (uint32_t)ni * (8u * 80u) + (uint32_t)kc * 32u);
            #pragma unroll
            for (int mi = 0; mi < 4; ++mi)
                #pragma unroll
                for (int ni = 0; ni < 4; ++ni)
                    mma16816(acc[mi][ni], afr[mi], bfr[ni]);
        }
    }

    const int rbase = bm + wm + (lane >> 2);
    const int cbase = bn + wn + (lane & 3) * 2;
    #pragma unroll
    for (int mi = 0; mi < 4; ++mi) {
        #pragma unroll
        for (int ni = 0; ni < 4; ++ni) {
            const int rr = rbase + mi * 16;
            const int cc = cbase + ni * 8;
            *(float2*)(C + (size_t)rr * NSRC + cc)       = make_float2(acc[mi][ni][0], acc[mi][ni][1]);
            *(float2*)(C + (size_t)(rr + 8) * NSRC + cc) = make_float2(acc[mi][ni][2], acc[mi][ni][3]);
        }
    }
}

// ---------------- 3. selection: two 8-element pre-sorted runs --------------
// Each thread sorts items 0-7 then 8-15 as u64 (ford<<3 | (7-i)) REUSING the
// same 8 sort registers (halves live regs vs one 16-wide sort). Selection
// takes the max of the two run heads (tie -> run A = lower original index).
__global__ void __launch_bounds__(256, 6) rank_kernel(
    const int* __restrict__ slab, const int* __restrict__ tlab)
{
    const int j   = blockIdx.x;
    const int tid = threadIdx.x;
    const int lane = tid & 31;
    const int w    = tid >> 5;

    __shared__ uint32_t s_ford[256 * 17];
    __shared__ unsigned char s_lab[NSRC];
    __shared__ unsigned long long s_k10[80];
    __shared__ unsigned long long s_k20[2][160];
    __shared__ int   s_t10[KNN];
    __shared__ int   s_a;
    __shared__ float s_sum[2];

    const float* simrow = g_simT + (size_t)j * NSRC;

    #pragma unroll
    for (int t = 0; t < 4; ++t) {
        const int i = tid + t * 256;
        int4 lb = ((const int4*)slab)[i];
        uchar4 uu;
        uu.x = (unsigned char)lb.x; uu.y = (unsigned char)lb.y;
        uu.z = (unsigned char)lb.z; uu.w = (unsigned char)lb.w;
        ((uchar4*)s_lab)[i] = uu;
    }

    const int base = w * 512 + lane * 16;
    const int fbase = tid * 17;
    const float4* rp = (const float4*)(simrow + base);

    unsigned idxp[2];
    #pragma unroll 1
    for (int r = 0; r < 2; ++r) {
        unsigned long long s[8];
        {
            const float4 v0 = rp[2 * r], v1 = rp[2 * r + 1];
            s[0] = ((unsigned long long)ford(v0.x) << 3) | 7u;
            s[1] = ((unsigned long long)ford(v0.y) << 3) | 6u;
            s[2] = ((unsigned long long)ford(v0.z) << 3) | 5u;
            s[3] = ((unsigned long long)ford(v0.w) << 3) | 4u;
            s[4] = ((unsigned long long)ford(v1.x) << 3) | 3u;
            s[5] = ((unsigned long long)ford(v1.y) << 3) | 2u;
            s[6] = ((unsigned long long)ford(v1.z) << 3) | 1u;
            s[7] = ((unsigned long long)ford(v1.w) << 3) | 0u;
        }
        #pragma unroll
        for (int k = 2; k <= 8; k <<= 1) {
            #pragma unroll
            for (int j2 = k >> 1; j2 > 0; j2 >>= 1) {
                #pragma unroll
                for (int i = 0; i < 8; ++i) {
                    const int l = i ^ j2;
                    if (l > i) {
                        const bool asc = (i & k) != 0;
                        const bool sw = asc ? (s[i] > s[l]) : (s[i] < s[l]);
                        if (sw) { unsigned long long t = s[i]; s[i] = s[l]; s[l] = t; }
                    }
                }
            }
        }
        unsigned ip = 0u;
        #pragma unroll
        for (int p = 0; p < 8; ++p) {
            s_ford[fbase + 8 * r + p] = (uint32_t)(s[p] >> 3);
            ip |= (unsigned)(7 - (int)(s[p] & 7ull)) << (4 * p);
        }
        idxp[r] = ip;
    }
    __syncthreads();   // also covers s_lab

    // ---- top-10 overall ---------------------------------------------------
    {
        unsigned remA = 0xFFu, remB = 0xFFu;
        #pragma unroll 1
        for (int it = 0; it < KNN; ++it) {
            const int pA = __ffs(remA | 0x100u) - 1;     // 8 if empty (in-bounds)
            const int pB = __ffs(remB | 0x100u) - 1;     // fbase+16 pad if empty
            const uint32_t kA = remA ? s_ford[fbase + pA] : 0u;
            const uint32_t kB = remB ? s_ford[fbase + 8 + pB] : 0u;
            const bool useA = (kA >= kB);
            const uint32_t best = useA ? kA : kB;
            const uint32_t m = __reduce_max_sync(0xffffffffu, best);
            const unsigned msk = __ballot_sync(0xffffffffu, best == m);
            if (lane == __ffs(msk) - 1) {
                const int orig = useA ? (int)((idxp[0] >> (4 * pA)) & 15u)
                                      : 8 + (int)((idxp[1] >> (4 * pB)) & 15u);
                s_k10[w * KNN + it] =
                    ((unsigned long long)m << 12) | (unsigned)(4095 - (base + orig));
                if (useA) remA &= remA - 1; else remB &= remB - 1;
            }
        }
    }
    __syncthreads();

    // ---- warp 0: merge 80 candidates -> global top-10, assign label -------
    if (w == 0) {
        unsigned long long mk[3];
        mk[0] = s_k10[lane];
        mk[1] = s_k10[lane + 32];
        mk[2] = (lane < 16) ? s_k10[lane + 64] : 0ull;
        unsigned int al = 7u;
        #pragma unroll 1
        for (int it = 0; it < KNN; ++it) {
            unsigned long long b = 0ull;
            #pragma unroll
            for (int t = 0; t < 3; ++t)
                if ((al >> t) & 1u) b = (mk[t] > b) ? mk[t] : b;
            unsigned long long key = wmax(b);
            if (lane == 0) s_t10[it] = 4095 - (int)(key & 0xFFFu);
            #pragma unroll
            for (int t = 0; t < 3; ++t)
                if (mk[t] == key) al &= ~(1u << t);
        }
        if (lane == 0) {
            int cls[KNN];
            #pragma unroll
            for (int k = 0; k < KNN; ++k) cls[k] = s_lab[s_t10[k]];
            int bestc = 1000, bestn = 0;
            #pragma unroll 1
            for (int k = 0; k < KNN; ++k) {
                int n = 0;
                #pragma unroll
                for (int l = 0; l < KNN; ++l) n += (cls[l] == cls[k]);
                if (n > bestn || (n == bestn && cls[k] < bestc)) { bestn = n; bestc = cls[k]; }
            }
            s_a = bestc;
            g_assigned[j] = bestc;
            if (bestc == tlab[j]) atomicAdd(&g_nc, 1);
        }
    }
    __syncthreads();
    const int a = s_a;

    // ---- class membership mapped through the sorted permutations ----------
    unsigned maskA = 0u, maskB = 0u;
    #pragma unroll
    for (int p = 0; p < 8; ++p) {
        const int oa = (int)((idxp[0] >> (4 * p)) & 15u);
        const int ob = 8 + (int)((idxp[1] >> (4 * p)) & 15u);
        maskA |= (s_lab[base + oa] == a) ? (1u << p) : 0u;
        maskB |= (s_lab[base + ob] == a) ? (1u << p) : 0u;
    }

    // ---- masked top-20 (in-class / out-of-class) --------------------------
    #pragma unroll 1
    for (int pass = 0; pass < 2; ++pass) {
        unsigned remA = pass ? (0xFFu & ~maskA) : maskA;
        unsigned remB = pass ? (0xFFu & ~maskB) : maskB;
        int it = 0;
        #pragma unroll 1
        for (; it < RK; ++it) {
            const int pA = __ffs(remA | 0x100u) - 1;
            const int pB = __ffs(remB | 0x100u) - 1;
            const uint32_t kA = remA ? s_ford[fbase + pA] : 0u;
            const uint32_t kB = remB ? s_ford[fbase + 8 + pB] : 0u;
            const bool useA = (kA >= kB);
            const uint32_t best = useA ? kA : kB;
            const uint32_t m = __reduce_max_sync(0xffffffffu, best);
            if (m == 0u) break;                         // warp exhausted
            const unsigned msk = __ballot_sync(0xffffffffu, best == m);
            if (lane == __ffs(msk) - 1) {
                const int orig = useA ? (int)((idxp[0] >> (4 * pA)) & 15u)
                                      : 8 + (int)((idxp[1] >> (4 * pB)) & 15u);
                s_k20[pass][w * RK + it] =
                    ((unsigned long long)m << 12) | (unsigned)(4095 - (base + orig));
                if (useA) remA &= remA - 1; else remB &= remB - 1;
            }
        }
        for (; it < RK; ++it)
            if (lane == 0) s_k20[pass][w * RK + it] = 0ull;
    }
    __syncthreads();

    // ---- warps 0,1 merge the two 160-candidate lists; gather sim0 via LDG -
    if (w < 2) {
        const float* sim0row = g_sim0T + (size_t)j * NSRC;
        const unsigned long long* keys = s_k20[w];
        unsigned long long mk[5];
        #pragma unroll
        for (int t = 0; t < 5; ++t) mk[t] = keys[lane + 32 * t];
        unsigned int al = 0x1Fu;
        float acc = 0.0f;
        #pragma unroll 1
        for (int it = 0; it < RK; ++it) {
            unsigned long long b = 0ull;
            #pragma unroll
            for (int t = 0; t < 5; ++t)
                if ((al >> t) & 1u) b = (mk[t] > b) ? mk[t] : b;
            unsigned long long key = wmax(b);
            const unsigned int f = (unsigned)(key >> 12);
            if (f == 0u || f == FORD_NEGINF) break;
            acc += __ldg(sim0row + (4095 - (int)(key & 0xFFFu)));
            #pragma unroll
            for (int t = 0; t < 5; ++t)
                if (mk[t] == key) al &= ~(1u << t);
        }
        if (lane == 0) s_sum[w] = acc;
    }
    __syncthreads();
    if (tid == 0) g_scores[j] = s_sum[0] / s_sum[1];
}

// ---------------- 4. exact top-2048 membership ------------------------------
__global__ void __launch_bounds__(256) select_kernel()
{
    const int j = blockIdx.x;
    const int tid = threadIdx.x;
    __shared__ int sr[8];
    const float sj = g_scores[j];
    int c = 0;
    for (int i = tid; i < NTGT; i += 256) {
        const float si = g_scores[i];
        if (si > sj || (si == sj && i < j)) ++c;
    }
    #pragma unroll
    for (int o = 16; o; o >>= 1) c += __shfl_down_sync(0xffffffffu, c, o);
    if ((tid & 31) == 0) sr[tid >> 5] = c;
    __syncthreads();
    if (tid == 0) {
        int r = 0;
        #pragma unroll
        for (int w = 0; w < 8; ++w) r += sr[w];
        g_sel[j] = (r < TOPN) ? 1 : 0;
    }
}

// ---------------- 5. contrast: fixed shift (sim0 = cosine <= 1) ------------
__global__ void __launch_bounds__(256) contrast_kernel(const int* __restrict__ slab)
{
    const int j = blockIdx.x;
    const int tid = threadIdx.x;
    __shared__ float s_pA[8];
    __shared__ float s_pM[8];

    if (!g_sel[j]) { if (tid == 0) g_logt[j] = 0.0f; return; }

    const float* row = g_sim0T + (size_t)j * NSRC;
    const int a = g_assigned[j];

    float eA = 0.0f, eM = 0.0f;
    const float itau = 1.0f / TAU;
    for (int i = tid; i < NSRC; i += 256) {
        const float e = expf((row[i] - 1.0f) * itau);   // |sim0|<=1 -> exp>=e^-40
        eA += e;
        if (slab[i] == a) eM += e;
    }
    #pragma unroll
    for (int o = 16; o; o >>= 1) {
        eA += __shfl_down_sync(0xffffffffu, eA, o);
        eM += __shfl_down_sync(0xffffffffu, eM, o);
    }
    if ((tid & 31) == 0) { s_pA[tid >> 5] = eA; s_pM[tid >> 5] = eM; }
    __syncthreads();
    if (tid == 0) {
        float tA = 0.0f, tM = 0.0f;
        #pragma unroll
        for (int w = 0; w < 8; ++w) { tA += s_pA[w]; tM += s_pM[w]; }
        g_logt[j] = logf(tM / tA + EPSL);
    }
}

// ---------------- 6. final deterministic reduction --------------------------
__global__ void __launch_bounds__(256) finalize_kernel(float* out, int out_size)
{
    const int tid = threadIdx.x;
    __shared__ float sr[8];
    float acc = 0.0f;
    for (int i = tid; i < NTGT; i += 256) acc += g_logt[i];
    #pragma unroll
    for (int o = 16; o; o >>= 1) acc += __shfl_down_sync(0xffffffffu, acc, o);
    if ((tid & 31) == 0) sr[tid >> 5] = acc;
    __syncthreads();
    if (tid == 0) {
        float tot = 0.0f;
        #pragma unroll
        for (int w = 0; w < 8; ++w) tot += sr[w];
        out[0] = -(tot / (float)TOPN);
        if (out_size > 1) out[1] = (float)g_nc;
    }
}

// ---------------- host launcher ---------------------------------------------
extern "C" void kernel_launch(void* const* d_in, const int* in_sizes, int n_in,
                              void* d_out, int out_size)
{
    const float* src  = (const float*)d_in[0];
    const int*   slab = (const int*)  d_in[1];
    const float* tgt  = (const float*)d_in[2];
    const float* tgt0 = (const float*)d_in[3];
    const int*   tlab = (const int*)  d_in[4];
    float* out = (float*)d_out;

    cudaFuncSetAttribute(gemm_f16, cudaFuncAttributeMaxDynamicSharedMemorySize,
                         GEMM_SMEM);

    normalize_k<<<dim3(NSRC, 3), 128>>>(src, tgt, tgt0);
    gemm_f16<<<dim3(32, 32, 2), 256, GEMM_SMEM>>>(KSPL);  // simT + sim0T
    rank_kernel<<<NTGT, 256>>>(slab, tlab);
    select_kernel<<<NTGT, 256>>>();
    contrast_kernel<<<NTGT, 256>>>(slab);
    finalize_kernel<<<1, 256>>>(out, out_size);
}

// round 16
// speedup vs baseline: 1.3521x; 1.0268x over previous
#include <cuda_runtime.h>
#include <cuda_fp16.h>
#include <math.h>
#include <stdint.h>

#define NSRC 4096
#define NTGT 4096
#define DIM  512
#define KSPL 1536          // 3-product fp16 split-K (err ~1e-8, = fp32 baseline)
#define NCLS 64
#define KNN  10
#define RK   20
#define TOPN 2048
#define TAU  0.05f
#define EPSL 1e-6f

#define FORD_NEGINF 0x007FFFFFu

// ---------------- scratch (device globals; allocation-free) ----------------
__device__ __half g_T16 [(size_t)NTGT * KSPL];  // T  split [a0|a0|a1]
__device__ __half g_T016[(size_t)NTGT * KSPL];  // T0 split [a0|a0|a1]
__device__ __half g_S16 [(size_t)NSRC * KSPL];  // S  split [b0|b1|b0] (shared B)
__device__ float g_simT [ (size_t)NTGT * NSRC ];
__device__ float g_sim0T[ (size_t)NTGT * NSRC ];
__device__ int   g_assigned[NTGT];
__device__ float g_scores[NTGT];
__device__ float g_logt[NTGT];
__device__ int   g_nc;

// ---------------- helpers ---------------------------------------------------
__device__ __forceinline__ unsigned int ford(float f) {
    unsigned int u = __float_as_uint(f);
    return (u & 0x80000000u) ? ~u : (u | 0x80000000u);
}
__device__ __forceinline__ unsigned long long wmax(unsigned long long k) {
    #pragma unroll
    for (int o = 16; o; o >>= 1) {
        unsigned long long t = __shfl_xor_sync(0xffffffffu, k, o);
        if (t > k) k = t;
    }
    return k;
}
__device__ __forceinline__ uint32_t smem_u32(const void* p) {
    uint32_t a;
    asm("{ .reg .u64 t; cvta.to.shared.u64 t, %1; cvt.u32.u64 %0, t; }" : "=r"(a) : "l"(p));
    return a;
}
__device__ __forceinline__ void ldsm4(uint32_t* r, uint32_t addr) {
    asm volatile("ldmatrix.sync.aligned.m8n8.x4.shared.b16 {%0,%1,%2,%3}, [%4];"
        : "=r"(r[0]), "=r"(r[1]), "=r"(r[2]), "=r"(r[3]) : "r"(addr));
}
__device__ __forceinline__ void ldsm2(uint32_t* r, uint32_t addr) {
    asm volatile("ldmatrix.sync.aligned.m8n8.x2.shared.b16 {%0,%1}, [%2];"
        : "=r"(r[0]), "=r"(r[1]) : "r"(addr));
}
__device__ __forceinline__ void mma16816(float* c, const uint32_t* a, const uint32_t* b) {
    asm volatile("mma.sync.aligned.m16n8k16.row.col.f32.f16.f16.f32 "
        "{%0,%1,%2,%3}, {%4,%5,%6,%7}, {%8,%9}, {%0,%1,%2,%3};"
        : "+f"(c[0]), "+f"(c[1]), "+f"(c[2]), "+f"(c[3])
        : "r"(a[0]), "r"(a[1]), "r"(a[2]), "r"(a[3]), "r"(b[0]), "r"(b[1]));
}
#define CP_A16(dst, src) \
    asm volatile("cp.async.cg.shared.global [%0], [%1], 16;" :: "r"(dst), "l"(src) : "memory")
#define CP_COMMIT() asm volatile("cp.async.commit_group;" ::: "memory")
#define CP_WAIT1()  asm volatile("cp.async.wait_group 1;" ::: "memory")

// ---------------- 1. normalize rows + fp16 2-component split emission ------
__global__ void __launch_bounds__(128) normalize_k(
    const float* __restrict__ src, const float* __restrict__ tgt,
    const float* __restrict__ tgt0)
{
    const int r = blockIdx.x;
    const int m = blockIdx.y;
    if (r == 0 && m == 0 && threadIdx.x == 0) g_nc = 0;

    const float* in = (m == 0) ? src : (m == 1) ? tgt : tgt0;

    const float4 v = ((const float4*)(in + (size_t)r * DIM))[threadIdx.x];
    float s = v.x*v.x + v.y*v.y + v.z*v.z + v.w*v.w;
    #pragma unroll
    for (int o = 16; o; o >>= 1) s += __shfl_down_sync(0xffffffffu, s, o);
    __shared__ float ws[4];
    if ((threadIdx.x & 31) == 0) ws[threadIdx.x >> 5] = s;
    __syncthreads();
    const float inv = 1.0f / sqrtf(ws[0] + ws[1] + ws[2] + ws[3]);
    float o4[4] = { v.x * inv, v.y * inv, v.z * inv, v.w * inv };

    __half c0[4], c1[4];
    #pragma unroll
    for (int t = 0; t < 4; ++t) {
        c0[t] = __float2half_rn(o4[t]);
        c1[t] = __float2half_rn(o4[t] - __half2float(c0[t]));
    }
    const int c = threadIdx.x * 4;
    if (m == 0) {            // source S (shared B): [b0 | b1 | b0]
        __half* p = g_S16 + (size_t)r * KSPL;
        #pragma unroll
        for (int t = 0; t < 4; ++t) {
            p[c+t] = c0[t]; p[c+t+512] = c1[t]; p[c+t+1024] = c0[t];
        }
    } else {                 // T / T0: [a0 | a0 | a1]
        __half* p = ((m == 1) ? g_T16 : g_T016) + (size_t)r * KSPL;
        #pragma unroll
        for (int t = 0; t < 4; ++t) {
            p[c+t] = c0[t]; p[c+t+512] = c0[t]; p[c+t+1024] = c1[t];
        }
    }
}

// ---------------- 2. fp16 mma.sync GEMM (R10 config; both C's in one grid) -
#define ST_BYTES 20480
#define GEMM_SMEM (3 * ST_BYTES)   // 61440
__global__ void __launch_bounds__(256) gemm_f16(int K)
{
    extern __shared__ char sm[];
    const int which = blockIdx.z;
    const __half* __restrict__ A = which ? g_T016 : g_T16;
    const __half* __restrict__ B = g_S16;
    float* __restrict__ C = which ? g_sim0T : g_simT;

    const int tid = threadIdx.x;
    const int bm = blockIdx.y * 128;
    const int bn = blockIdx.x * 128;
    const int lr = tid >> 1;
    const int lh = tid & 1;

    const __half* Ag = A + (size_t)(bm + lr) * K + lh * 16;
    const __half* Bg = B + (size_t)(bn + lr) * K + lh * 16;

    const uint32_t sbase = smem_u32(sm);
    const uint32_t awr = sbase + (uint32_t)lr * 80u + (uint32_t)lh * 32u;
    const uint32_t bwr = awr + 10240u;

    const int w = tid >> 5, lane = tid & 31;
    const int wm = (w >> 2) * 64;
    const int wn = (w & 3) * 32;
    const uint32_t aoff = (uint32_t)(wm + (lane & 15)) * 80u + (uint32_t)(lane >> 4) * 16u;
    const uint32_t boff = 10240u + (uint32_t)(wn + (lane & 7)) * 80u
                        + (uint32_t)((lane >> 3) & 1) * 16u;

    const int NKT = K >> 5;

    #pragma unroll
    for (int t = 0; t < 2; ++t) {
        const uint32_t st = (uint32_t)t * ST_BYTES;
        const __half* as = Ag + t * 32;
        const __half* bs = Bg + t * 32;
        CP_A16(awr + st, as);
        CP_A16(awr + st + 16u, as + 8);
        CP_A16(bwr + st, bs);
        CP_A16(bwr + st + 16u, bs + 8);
        CP_COMMIT();
    }

    float acc[4][4][4];
    #pragma unroll
    for (int mi = 0; mi < 4; ++mi)
        #pragma unroll
        for (int ni = 0; ni < 4; ++ni)
            #pragma unroll
            for (int t = 0; t < 4; ++t) acc[mi][ni][t] = 0.0f;

    #pragma unroll 1
    for (int kt = 0; kt < NKT; ++kt) {
        CP_WAIT1();
        __syncthreads();
        if (kt + 2 < NKT) {
            const uint32_t st = (uint32_t)((kt + 2) % 3) * ST_BYTES;
            const __half* as = Ag + (kt + 2) * 32;
            const __half* bs = Bg + (kt + 2) * 32;
            CP_A16(awr + st, as);
            CP_A16(awr + st + 16u, as + 8);
            CP_A16(bwr + st, bs);
            CP_A16(bwr + st + 16u, bs + 8);
        }
        CP_COMMIT();

        const uint32_t st = (uint32_t)(kt % 3) * ST_BYTES;
        const uint32_t abase = sbase + st + aoff;
        const uint32_t bbase = sbase + st + boff;
        #pragma unroll
        for (int kc = 0; kc < 2; ++kc) {
            uint32_t afr[4][4], bfr[4][2];
            #pragma unroll
            for (int mi = 0; mi < 4; ++mi)
                ldsm4(afr[mi], abase + (uint32_t)mi * (16u * 80u) + (uint32_t)kc * 32u);
            #pragma unroll
            for (int ni = 0; ni < 4; ++ni)
                ldsm2(bfr[ni], bbase + (uint32_t)ni * (8u * 80u) + (uint32_t)kc * 32u);
            #pragma unroll
            for (int mi = 0; mi < 4; ++mi)
                #pragma unroll
                for (int ni = 0; ni < 4; ++ni)
                    mma16816(acc[mi][ni], afr[mi], bfr[ni]);
        }
    }

    const int rbase = bm + wm + (lane >> 2);
    const int cbase = bn + wn + (lane & 3) * 2;
    #pragma unroll
    for (int mi = 0; mi < 4; ++mi) {
        #pragma unroll
        for (int ni = 0; ni < 4; ++ni) {
            const int rr = rbase + mi * 16;
            const int cc = cbase + ni * 8;
            *(float2*)(C + (size_t)rr * NSRC + cc)       = make_float2(acc[mi][ni][0], acc[mi][ni][1]);
            *(float2*)(C + (size_t)(rr + 8) * NSRC + cc) = make_float2(acc[mi][ni][2], acc[mi][ni][3]);
        }
    }
}

// ---------------- 3. selection: sorted runs + cached heads -----------------
// Two 8-element pre-sorted runs per thread (R15-validated). NEW: run heads
// (kA,pA)/(kB,pB) cached in registers; only the winning lane advances its
// mask and reloads one head from smem. Tie rules unchanged: kA>=kB prefers
// run A (lower index); redux+ballot picks lowest lane.
__global__ void __launch_bounds__(256, 6) rank_kernel(
    const int* __restrict__ slab, const int* __restrict__ tlab)
{
    const int j   = blockIdx.x;
    const int tid = threadIdx.x;
    const int lane = tid & 31;
    const int w    = tid >> 5;

    __shared__ uint32_t s_ford[256 * 17];
    __shared__ unsigned char s_lab[NSRC];
    __shared__ unsigned long long s_k10[80];
    __shared__ unsigned long long s_k20[2][160];
    __shared__ int   s_t10[KNN];
    __shared__ int   s_a;
    __shared__ float s_sum[2];

    const float* simrow = g_simT + (size_t)j * NSRC;

    #pragma unroll
    for (int t = 0; t < 4; ++t) {
        const int i = tid + t * 256;
        int4 lb = ((const int4*)slab)[i];
        uchar4 uu;
        uu.x = (unsigned char)lb.x; uu.y = (unsigned char)lb.y;
        uu.z = (unsigned char)lb.z; uu.w = (unsigned char)lb.w;
        ((uchar4*)s_lab)[i] = uu;
    }

    const int base = w * 512 + lane * 16;
    const int fbase = tid * 17;
    const float4* rp = (const float4*)(simrow + base);

    unsigned idxp[2];
    #pragma unroll 1
    for (int r = 0; r < 2; ++r) {
        unsigned long long s[8];
        {
            const float4 v0 = rp[2 * r], v1 = rp[2 * r + 1];
            s[0] = ((unsigned long long)ford(v0.x) << 3) | 7u;
            s[1] = ((unsigned long long)ford(v0.y) << 3) | 6u;
            s[2] = ((unsigned long long)ford(v0.z) << 3) | 5u;
            s[3] = ((unsigned long long)ford(v0.w) << 3) | 4u;
            s[4] = ((unsigned long long)ford(v1.x) << 3) | 3u;
            s[5] = ((unsigned long long)ford(v1.y) << 3) | 2u;
            s[6] = ((unsigned long long)ford(v1.z) << 3) | 1u;
            s[7] = ((unsigned long long)ford(v1.w) << 3) | 0u;
        }
        #pragma unroll
        for (int k = 2; k <= 8; k <<= 1) {
            #pragma unroll
            for (int j2 = k >> 1; j2 > 0; j2 >>= 1) {
                #pragma unroll
                for (int i = 0; i < 8; ++i) {
                    const int l = i ^ j2;
                    if (l > i) {
                        const bool asc = (i & k) != 0;
                        const bool sw = asc ? (s[i] > s[l]) : (s[i] < s[l]);
                        if (sw) { unsigned long long t = s[i]; s[i] = s[l]; s[l] = t; }
                    }
                }
            }
        }
        unsigned ip = 0u;
        #pragma unroll
        for (int p = 0; p < 8; ++p) {
            s_ford[fbase + 8 * r + p] = (uint32_t)(s[p] >> 3);
            ip |= (unsigned)(7 - (int)(s[p] & 7ull)) << (4 * p);
        }
        idxp[r] = ip;
    }
    __syncthreads();   // also covers s_lab

    // ---- top-10 overall (cached heads) ------------------------------------
    {
        unsigned remA = 0xFFu, remB = 0xFFu;
        int pA = 0, pB = 0;
        uint32_t kA = s_ford[fbase], kB = s_ford[fbase + 8];
        #pragma unroll 1
        for (int it = 0; it < KNN; ++it) {
            const bool useA = (kA >= kB);
            const uint32_t best = useA ? kA : kB;
            const uint32_t m = __reduce_max_sync(0xffffffffu, best);
            const unsigned msk = __ballot_sync(0xffffffffu, best == m);
            if (lane == __ffs(msk) - 1) {
                const int orig = useA ? (int)((idxp[0] >> (4 * pA)) & 15u)
                                      : 8 + (int)((idxp[1] >> (4 * pB)) & 15u);
                s_k10[w * KNN + it] =
                    ((unsigned long long)m << 12) | (unsigned)(4095 - (base + orig));
                if (useA) {
                    remA &= remA - 1;
                    pA = __ffs(remA | 0x100u) - 1;
                    kA = remA ? s_ford[fbase + pA] : 0u;
                } else {
                    remB &= remB - 1;
                    pB = __ffs(remB | 0x100u) - 1;
                    kB = remB ? s_ford[fbase + 8 + pB] : 0u;
                }
            }
        }
    }
    __syncthreads();

    // ---- warp 0: merge 80 candidates -> global top-10, assign label -------
    if (w == 0) {
        unsigned long long mk[3];
        mk[0] = s_k10[lane];
        mk[1] = s_k10[lane + 32];
        mk[2] = (lane < 16) ? s_k10[lane + 64] : 0ull;
        unsigned int al = 7u;
        #pragma unroll 1
        for (int it = 0; it < KNN; ++it) {
            unsigned long long b = 0ull;
            #pragma unroll
            for (int t = 0; t < 3; ++t)
                if ((al >> t) & 1u) b = (mk[t] > b) ? mk[t] : b;
            unsigned long long key = wmax(b);
            if (lane == 0) s_t10[it] = 4095 - (int)(key & 0xFFFu);
            #pragma unroll
            for (int t = 0; t < 3; ++t)
                if (mk[t] == key) al &= ~(1u << t);
        }
        if (lane == 0) {
            int cls[KNN];
            #pragma unroll
            for (int k = 0; k < KNN; ++k) cls[k] = s_lab[s_t10[k]];
            int bestc = 1000, bestn = 0;
            #pragma unroll 1
            for (int k = 0; k < KNN; ++k) {
                int n = 0;
                #pragma unroll
                for (int l = 0; l < KNN; ++l) n += (cls[l] == cls[k]);
                if (n > bestn || (n == bestn && cls[k] < bestc)) { bestn = n; bestc = cls[k]; }
            }
            s_a = bestc;
            g_assigned[j] = bestc;
            if (bestc == tlab[j]) atomicAdd(&g_nc, 1);
        }
    }
    __syncthreads();
    const int a = s_a;

    // ---- class membership mapped through the sorted permutations ----------
    unsigned maskA = 0u, maskB = 0u;
    #pragma unroll
    for (int p = 0; p < 8; ++p) {
        const int oa = (int)((idxp[0] >> (4 * p)) & 15u);
        const int ob = 8 + (int)((idxp[1] >> (4 * p)) & 15u);
        maskA |= (s_lab[base + oa] == a) ? (1u << p) : 0u;
        maskB |= (s_lab[base + ob] == a) ? (1u << p) : 0u;
    }

    // ---- masked top-20 (in-class / out-of-class), cached heads ------------
    #pragma unroll 1
    for (int pass = 0; pass < 2; ++pass) {
        unsigned remA = pass ? (0xFFu & ~maskA) : maskA;
        unsigned remB = pass ? (0xFFu & ~maskB) : maskB;
        int pA = __ffs(remA | 0x100u) - 1;
        int pB = __ffs(remB | 0x100u) - 1;
        uint32_t kA = remA ? s_ford[fbase + pA] : 0u;
        uint32_t kB = remB ? s_ford[fbase + 8 + pB] : 0u;
        int it = 0;
        #pragma unroll 1
        for (; it < RK; ++it) {
            const bool useA = (kA >= kB);
            const uint32_t best = useA ? kA : kB;
            const uint32_t m = __reduce_max_sync(0xffffffffu, best);
            if (m == 0u) break;                         // warp exhausted
            const unsigned msk = __ballot_sync(0xffffffffu, best == m);
            if (lane == __ffs(msk) - 1) {
                const int orig = useA ? (int)((idxp[0] >> (4 * pA)) & 15u)
                                      : 8 + (int)((idxp[1] >> (4 * pB)) & 15u);
                s_k20[pass][w * RK + it] =
                    ((unsigned long long)m << 12) | (unsigned)(4095 - (base + orig));
                if (useA) {
                    remA &= remA - 1;
                    pA = __ffs(remA | 0x100u) - 1;
                    kA = remA ? s_ford[fbase + pA] : 0u;
                } else {
                    remB &= remB - 1;
                    pB = __ffs(remB | 0x100u) - 1;
                    kB = remB ? s_ford[fbase + 8 + pB] : 0u;
                }
            }
        }
        for (; it < RK; ++it)
            if (lane == 0) s_k20[pass][w * RK + it] = 0ull;
    }
    __syncthreads();

    // ---- warps 0,1 merge the two 160-candidate lists; gather sim0 via LDG -
    if (w < 2) {
        const float* sim0row = g_sim0T + (size_t)j * NSRC;
        const unsigned long long* keys = s_k20[w];
        unsigned long long mk[5];
        #pragma unroll
        for (int t = 0; t < 5; ++t) mk[t] = keys[lane + 32 * t];
        unsigned int al = 0x1Fu;
        float acc = 0.0f;
        #pragma unroll 1
        for (int it = 0; it < RK; ++it) {
            unsigned long long b = 0ull;
            #pragma unroll
            for (int t = 0; t < 5; ++t)
                if ((al >> t) & 1u) b = (mk[t] > b) ? mk[t] : b;
            unsigned long long key = wmax(b);
            const unsigned int f = (unsigned)(key >> 12);
            if (f == 0u || f == FORD_NEGINF) break;
            acc += __ldg(sim0row + (4095 - (int)(key & 0xFFFu)));
            #pragma unroll
            for (int t = 0; t < 5; ++t)
                if (mk[t] == key) al &= ~(1u << t);
        }
        if (lane == 0) s_sum[w] = acc;
    }
    __syncthreads();
    if (tid == 0) g_scores[j] = s_sum[0] / s_sum[1];
}

// ---------------- 4. contrast with fused top-2048 membership ---------------
__global__ void __launch_bounds__(256) contrast_kernel(const int* __restrict__ slab)
{
    const int j = blockIdx.x;
    const int tid = threadIdx.x;
    __shared__ int   sr[8];
    __shared__ int   s_r;
    __shared__ float s_pA[8];
    __shared__ float s_pM[8];

    // exact lax.top_k membership: rank = #(si>sj) + #(si==sj && i<j)
    const float sj = g_scores[j];
    int c = 0;
    for (int i = tid; i < NTGT; i += 256) {
        const float si = g_scores[i];
        if (si > sj || (si == sj && i < j)) ++c;
    }
    #pragma unroll
    for (int o = 16; o; o >>= 1) c += __shfl_down_sync(0xffffffffu, c, o);
    if ((tid & 31) == 0) sr[tid >> 5] = c;
    __syncthreads();
    if (tid == 0) {
        int r = 0;
        #pragma unroll
        for (int w = 0; w < 8; ++w) r += sr[w];
        s_r = r;
    }
    __syncthreads();
    if (s_r >= TOPN) { if (tid == 0) g_logt[j] = 0.0f; return; }

    const float* row = g_sim0T + (size_t)j * NSRC;
    const int a = g_assigned[j];

    float eA = 0.0f, eM = 0.0f;
    const float itau = 1.0f / TAU;
    for (int i = tid; i < NSRC; i += 256) {
        const float e = expf((row[i] - 1.0f) * itau);   // |sim0|<=1 -> exp>=e^-40
        eA += e;
        if (slab[i] == a) eM += e;
    }
    #pragma unroll
    for (int o = 16; o; o >>= 1) {
        eA += __shfl_down_sync(0xffffffffu, eA, o);
        eM += __shfl_down_sync(0xffffffffu, eM, o);
    }
    if ((tid & 31) == 0) { s_pA[tid >> 5] = eA; s_pM[tid >> 5] = eM; }
    __syncthreads();
    if (tid == 0) {
        float tA = 0.0f, tM = 0.0f;
        #pragma unroll
        for (int w = 0; w < 8; ++w) { tA += s_pA[w]; tM += s_pM[w]; }
        g_logt[j] = logf(tM / tA + EPSL);
    }
}

// ---------------- 5. final deterministic reduction --------------------------
__global__ void __launch_bounds__(256) finalize_kernel(float* out, int out_size)
{
    const int tid = threadIdx.x;
    __shared__ float sr[8];
    float acc = 0.0f;
    for (int i = tid; i < NTGT; i += 256) acc += g_logt[i];
    #pragma unroll
    for (int o = 16; o; o >>= 1) acc += __shfl_down_sync(0xffffffffu, acc, o);
    if ((tid & 31) == 0) sr[tid >> 5] = acc;
    __syncthreads();
    if (tid == 0) {
        float tot = 0.0f;
        #pragma unroll
        for (int w = 0; w < 8; ++w) tot += sr[w];
        out[0] = -(tot / (float)TOPN);
        if (out_size > 1) out[1] = (float)g_nc;
    }
}

// ---------------- host launcher ---------------------------------------------
extern "C" void kernel_launch(void* const* d_in, const int* in_sizes, int n_in,
                              void* d_out, int out_size)
{
    const float* src  = (const float*)d_in[0];
    const int*   slab = (const int*)  d_in[1];
    const float* tgt  = (const float*)d_in[2];
    const float* tgt0 = (const float*)d_in[3];
    const int*   tlab = (const int*)  d_in[4];
    float* out = (float*)d_out;

    cudaFuncSetAttribute(gemm_f16, cudaFuncAttributeMaxDynamicSharedMemorySize,
                         GEMM_SMEM);

    normalize_k<<<dim3(NSRC, 3), 128>>>(src, tgt, tgt0);
    gemm_f16<<<dim3(32, 32, 2), 256, GEMM_SMEM>>>(KSPL);  // simT + sim0T
    rank_kernel<<<NTGT, 256>>>(slab, tlab);
    contrast_kernel<<<NTGT, 256>>>(slab);
    finalize_kernel<<<1, 256>>>(out, out_size);
}